// round 15
// baseline (speedup 1.0000x reference)
#include <cuda_runtime.h>
#include <cuda_bf16.h>
#include <math.h>
#include <stdint.h>

#define N_ITEMS 10000
#define NPAD    10112   // 79 * 128
#define DD      128
#define C2      256
#define D3      384
#define NBATCH  1024
#define HIST    100
#define NCHUNK  79
#define RJS     16
#define CPS     5       // chunks per split (last split gets 4)
#define IBLK    128
#define NIB     79      // NPAD / 128

// SMEM strides (bf16 elements)
#define QS  264         // Q row stride (256 + 8 pad), 528B
#define ES  136         // E tile row stride (128 + 8 pad), 272B

__device__ __forceinline__ uint32_t smem_to_u32(const void* p) {
    uint32_t a;
    asm("{ .reg .u64 t; cvta.to.shared.u64 t, %1; cvt.u32.u64 %0, t; }" : "=r"(a) : "l"(p));
    return a;
}
__device__ __forceinline__ void ldsm_x4(uint32_t r[4], uint32_t addr) {
    asm volatile("ldmatrix.sync.aligned.m8n8.x4.shared.b16 {%0,%1,%2,%3}, [%4];"
                 : "=r"(r[0]), "=r"(r[1]), "=r"(r[2]), "=r"(r[3]) : "r"(addr));
}
__device__ __forceinline__ void ldsm_x4_t(uint32_t r[4], uint32_t addr) {
    asm volatile("ldmatrix.sync.aligned.m8n8.x4.trans.shared.b16 {%0,%1,%2,%3}, [%4];"
                 : "=r"(r[0]), "=r"(r[1]), "=r"(r[2]), "=r"(r[3]) : "r"(addr));
}
__device__ __forceinline__ void mma_bf16(float* c, const uint32_t a[4],
                                         uint32_t b0, uint32_t b1) {
    asm volatile(
        "mma.sync.aligned.m16n8k16.row.col.f32.bf16.bf16.f32 "
        "{%0,%1,%2,%3}, {%4,%5,%6,%7}, {%8,%9}, {%0,%1,%2,%3};"
        : "+f"(c[0]), "+f"(c[1]), "+f"(c[2]), "+f"(c[3])
        : "r"(a[0]), "r"(a[1]), "r"(a[2]), "r"(a[3]), "r"(b0), "r"(b1));
}
#define CP_ASYNC16(dst, src) \
    asm volatile("cp.async.cg.shared.global [%0], [%1], 16;" :: "r"(dst), "l"(src))
#define CP_COMMIT()  asm volatile("cp.async.commit_group;" ::: "memory")
#define CP_WAIT0()   asm volatile("cp.async.wait_group 0;" ::: "memory")
#define STS32(addr, v) \
    asm volatile("st.shared.b32 [%0], %1;" :: "r"(addr), "r"(v) : "memory")

// ---------------- scratch (device globals; loaded eagerly by Preload) ------
__device__ __nv_bfloat16 g_qbf[(size_t)NPAD * C2];
__device__ __nv_bfloat16 g_E[(size_t)NIB * NIB * IBLK * IBLK];  // 204.5 MB
__device__ float g_colpart[NCHUNK][C2];
__device__ float g_colsum[C2];
__device__ __nv_bfloat16 g_part[(size_t)RJS * NPAD * C2];
__device__ float g_denp2[(size_t)NIB * NPAD];
__device__ float g_invden[N_ITEMS];
__device__ float g_cat[(size_t)N_ITEMS * D3];
__device__ __nv_bfloat16 g_catb[(size_t)N_ITEMS * D3];
__device__ __nv_bfloat16 g_keb[(size_t)N_ITEMS * D3];
__device__ float g_tgt[(size_t)2 * NBATCH * D3];
__device__ __nv_bfloat16 g_tgtb[(size_t)2 * NBATCH * D3];
__device__ __nv_bfloat16 g_tgtl[(size_t)2 * NBATCH * D3];
__device__ float g_qp[(size_t)2 * NBATCH * D3];
__device__ float g_uv[(size_t)2 * NBATCH * D3];
__device__ __nv_bfloat16 g_wkb[D3 * D3];
__device__ __nv_bfloat16 g_wqb[D3 * D3];
__device__ __nv_bfloat16 g_wvh[D3 * D3];   // Wv^T hi
__device__ __nv_bfloat16 g_wvl[D3 * D3];   // Wv^T lo

// expm1 for tiny args (|x| ~ 1e-4 here); guarded fallback.
__device__ __forceinline__ float fexpm1(float x) {
    if (fabsf(x) > 0.4f) return __expf(x) - 1.f;
    return x * (1.f + x * (0.5f + x * (0.16666667f + x * 0.04166667f)));
}

// ---------------- prep: bf16 q = [emb_in | emb_out], zero pad rows ----------
__global__ void k_prep(const float* __restrict__ emb_in,
                       const float* __restrict__ emb_out) {
    int gid = blockIdx.x * blockDim.x + threadIdx.x;
    if (gid < NPAD * C2) {
        int i = gid >> 8, c = gid & 255;
        float q = 0.f;
        if (i < N_ITEMS)
            q = (c < DD) ? emb_in[(size_t)i * DD + c] : emb_out[(size_t)i * DD + c - DD];
        g_qbf[gid] = __float2bfloat16(q);
    }
}

__global__ void k_colsum() {
    int b = blockIdx.x, c = threadIdx.x;
    float s = 0.f;
    for (int r = 0; r < 128; r++)
        s += __bfloat162float(g_qbf[(size_t)(b * 128 + r) * C2 + c]);
    g_colpart[b][c] = s;
}
__global__ void k_colred() {
    int c = threadIdx.x;
    float s = 0.f;
    for (int b = 0; b < NCHUNK; b++) s += g_colpart[b][c];
    g_colsum[c] = s;
}

// weights: bf16 Wk, Wq; Wv^T split hi/lo bf16
__global__ void k_wprep(const float* __restrict__ Wk, const float* __restrict__ Wq,
                        const float* __restrict__ Wv) {
    int gid = blockIdx.x * blockDim.x + threadIdx.x;
    if (gid < D3 * D3) {
        g_wkb[gid] = __float2bfloat16(Wk[gid]);
        g_wqb[gid] = __float2bfloat16(Wq[gid]);
        int r = gid / D3, c = gid % D3;
        float v = Wv[gid];
        __nv_bfloat16 hi = __float2bfloat16(v);
        g_wvh[c * D3 + r] = hi;
        g_wvl[c * D3 + r] = __float2bfloat16(v - __bfloat162float(hi));
    }
}

// ======== phase A: upper-triangle score blocks (S symmetric!) ===============
// CTA (I, J), J >= I: GEMM1 S[128,128] = Qi . Kj^T; Ec = expm1(S/16) with
// row+col pad masks (-1); store Ec bf16 to g_E[I*NIB+J]; den partials:
// row sums -> slot J over block-I rows; col sums -> slot I over block-J rows.
#define SA_QI   0
#define SA_QJ   (SA_QI + IBLK * QS * 2)            // 67584
#define SA_E    (SA_QJ + IBLK * QS * 2)            // 135168
#define SA_DENB (SA_E + IBLK * ES * 2)             // 169984
#define SA_TOT  (SA_DENB + 2 * IBLK * 4)           // 171008

__global__ __launch_bounds__(256, 1) void k_scoreA() {
    int I = blockIdx.x, J = blockIdx.y;
    if (J < I) return;
    extern __shared__ char smem[];
    uint32_t sb = smem_to_u32(smem);
    const __nv_bfloat16* __restrict__ qg = g_qbf;
    int tid = threadIdx.x;
    int warp = tid >> 5, lane = tid & 31;
    int i0 = I * IBLK, j0 = J * IBLK;
    const int rgrp = warp >> 1, chalf = warp & 1;
    const int mbase = rgrp * 32;

    // load Qi; Qj only if off-diagonal
    for (int it = 0; it < 16; it++) {
        int idx = it * 256 + tid;
        int row = idx >> 5, c16 = idx & 31;
        uint4 v = *(const uint4*)(qg + (size_t)(i0 + row) * C2 + (c16 << 3));
        *(uint4*)(smem + SA_QI + row * (QS * 2) + c16 * 16) = v;
    }
    if (J != I) {
        for (int it = 0; it < 16; it++) {
            int idx = it * 256 + tid;
            int row = idx >> 5, c16 = idx & 31;
            uint4 v = *(const uint4*)(qg + (size_t)(j0 + row) * C2 + (c16 << 3));
            *(uint4*)(smem + SA_QJ + row * (QS * 2) + c16 * 16) = v;
        }
    }
    __syncthreads();
    uint32_t sQj = sb + ((J == I) ? SA_QI : SA_QJ);

    float den[4] = {0.f, 0.f, 0.f, 0.f};  // row-sum partials [mt][subrow]

#pragma unroll
    for (int hf = 0; hf < 2; hf++) {
        int qb = hf * 64 + chalf * 32;
        float s[8][4];
#pragma unroll
        for (int t = 0; t < 8; t++)
#pragma unroll
            for (int k = 0; k < 4; k++) s[t][k] = 0.f;
#pragma unroll
        for (int kk = 0; kk < 16; kk++) {
            int kc = kk * 16;
            int kcsrc = (128 + kc) & 255;
            uint32_t a0[4], a1[4];
            ldsm_x4(a0, sb + SA_QI + (mbase + (lane & 15)) * (QS * 2)
                            + (kc + ((lane >> 4) << 3)) * 2);
            ldsm_x4(a1, sb + SA_QI + (mbase + 16 + (lane & 15)) * (QS * 2)
                            + (kc + ((lane >> 4) << 3)) * 2);
#pragma unroll
            for (int t = 0; t < 2; t++) {
                uint32_t b[4];
                int nrow = qb + t * 16 + (lane & 7) + ((lane & 16) >> 1);
                int bc = kcsrc + (lane & 8);
                ldsm_x4(b, sQj + nrow * (QS * 2) + bc * 2);
                mma_bf16(s[2 * t],         a0, b[0], b[1]);
                mma_bf16(s[2 * t + 1],     a0, b[2], b[3]);
                mma_bf16(s[4 + 2 * t],     a1, b[0], b[1]);
                mma_bf16(s[4 + 2 * t + 1], a1, b[2], b[3]);
            }
        }
        // epilogue: mask pad rows AND cols -> -1; row dens; write full E tile
#pragma unroll
        for (int st = 0; st < 8; st++) {
            int mt = st >> 2, nt = st & 3;
            int jloc = qb + nt * 8 + ((lane & 3) << 1);
            int jg = j0 + jloc;
            int r0 = mbase + mt * 16 + (lane >> 2);
            bool iv0 = (i0 + r0) < N_ITEMS, iv1 = (i0 + r0 + 8) < N_ITEMS;
            bool jv0 = jg < N_ITEMS, jv1 = (jg + 1) < N_ITEMS;
            float f0 = (iv0 && jv0) ? fexpm1(s[st][0] * 0.0625f) : -1.f;
            float f1 = (iv0 && jv1) ? fexpm1(s[st][1] * 0.0625f) : -1.f;
            float f2 = (iv1 && jv0) ? fexpm1(s[st][2] * 0.0625f) : -1.f;
            float f3 = (iv1 && jv1) ? fexpm1(s[st][3] * 0.0625f) : -1.f;
            den[mt * 2 + 0] += f0 + f1;
            den[mt * 2 + 1] += f2 + f3;
            __nv_bfloat162 p01 = __floats2bfloat162_rn(f0, f1);
            __nv_bfloat162 p23 = __floats2bfloat162_rn(f2, f3);
            STS32(sb + SA_E + r0 * (ES * 2) + jloc * 2, *(uint32_t*)&p01);
            STS32(sb + SA_E + (r0 + 8) * (ES * 2) + jloc * 2, *(uint32_t*)&p23);
        }
    }
    __syncthreads();
    // store E tile to global (coalesced)
    {
        __nv_bfloat16* eb = g_E + ((size_t)I * NIB + J) * (IBLK * IBLK);
#pragma unroll
        for (int it = 0; it < 8; it++) {
            int idx = it * 256 + tid;
            int row = idx >> 4, c16 = idx & 15;
            uint4 v = *(const uint4*)(smem + SA_E + row * (ES * 2) + c16 * 16);
            *(uint4*)(eb + (size_t)row * IBLK + c16 * 8) = v;
        }
    }
    // column sums -> den contributions for block-J rows (slot I); skip on diag
    if (J != I && tid < IBLK) {
        float cs = 0.f;
        for (int r = 0; r < IBLK; r++)
            cs += __bfloat162float(
                *(const __nv_bfloat16*)(smem + SA_E + r * (ES * 2) + tid * 2));
        g_denp2[(size_t)I * NPAD + j0 + tid] = cs;
    }
    // row sums -> slot J over block-I rows
#pragma unroll
    for (int q = 0; q < 4; q++) {
        den[q] += __shfl_xor_sync(0xffffffffu, den[q], 1);
        den[q] += __shfl_xor_sync(0xffffffffu, den[q], 2);
    }
    if ((lane & 3) == 0) {
        float* db = (float*)(smem + SA_DENB) + chalf * IBLK;
#pragma unroll
        for (int mt = 0; mt < 2; mt++) {
            db[mbase + mt * 16 + (lane >> 2)]     = den[mt * 2 + 0];
            db[mbase + mt * 16 + 8 + (lane >> 2)] = den[mt * 2 + 1];
        }
    }
    __syncthreads();
    if (tid < IBLK) {
        const float* db = (const float*)(smem + SA_DENB);
        g_denp2[(size_t)J * NPAD + i0 + tid] = db[tid] + db[IBLK + tid];
    }
}

// ======== phase B: D2_I += Ec(I,J) . Q_J  (A from g_E; transposed if J<I) ===
#define SB_QJ0  0
#define SB_QJ1  (SB_QJ0 + IBLK * QS * 2)           // 67584
#define SB_E0   (SB_QJ1 + IBLK * QS * 2)           // 135168
#define SB_E1   (SB_E0 + IBLK * ES * 2)            // 169984
#define SB_TOT  (SB_E1 + IBLK * ES * 2)            // 204800

__global__ __launch_bounds__(256, 1) void k_flashB() {
    extern __shared__ char smem[];
    uint32_t sb = smem_to_u32(smem);
    const __nv_bfloat16* __restrict__ qg = g_qbf;
    int tid = threadIdx.x;
    int warp = tid >> 5, lane = tid & 31;
    int I = blockIdx.x;
    int i0 = I * IBLK;
    int split = blockIdx.y;
    int c0 = split * CPS;
    int c1 = min(NCHUNK, c0 + CPS);
    const int rgrp = warp >> 1, chalf = warp & 1;
    const int mbase = rgrp * 32;

    // prefetch chunk c0
    {
        int j0 = c0 * 128;
        for (int it = 0; it < 16; it++) {
            int idx = it * 256 + tid;
            int row = idx >> 5, c16 = idx & 31;
            CP_ASYNC16(sb + SB_QJ0 + row * (QS * 2) + c16 * 16,
                       qg + (size_t)(j0 + row) * C2 + (c16 << 3));
        }
        const __nv_bfloat16* eb = g_E +
            ((c0 >= I) ? ((size_t)I * NIB + c0) : ((size_t)c0 * NIB + I)) * (IBLK * IBLK);
        for (int it = 0; it < 8; it++) {
            int idx = it * 256 + tid;
            int row = idx >> 4, c16 = idx & 15;
            CP_ASYNC16(sb + SB_E0 + row * (ES * 2) + c16 * 16,
                       eb + (size_t)row * IBLK + c16 * 8);
        }
        CP_COMMIT();
    }

    float d2[128];
#pragma unroll
    for (int i = 0; i < 128; i++) d2[i] = 0.f;

    for (int jc = c0; jc < c1; jc++) {
        int buf = (jc - c0) & 1;
        uint32_t sQj = sb + (buf ? SB_QJ1 : SB_QJ0);
        uint32_t sE  = sb + (buf ? SB_E1 : SB_E0);
        CP_WAIT0();
        __syncthreads();
        if (jc + 1 < c1) {
            uint32_t dQj = sb + (buf ? SB_QJ0 : SB_QJ1);
            uint32_t dE  = sb + (buf ? SB_E0 : SB_E1);
            int jn = jc + 1;
            int j0n = jn * 128;
            for (int it = 0; it < 16; it++) {
                int idx = it * 256 + tid;
                int row = idx >> 5, c16 = idx & 31;
                CP_ASYNC16(dQj + row * (QS * 2) + c16 * 16,
                           qg + (size_t)(j0n + row) * C2 + (c16 << 3));
            }
            const __nv_bfloat16* eb = g_E +
                ((jn >= I) ? ((size_t)I * NIB + jn) : ((size_t)jn * NIB + I)) * (IBLK * IBLK);
            for (int it = 0; it < 8; it++) {
                int idx = it * 256 + tid;
                int row = idx >> 4, c16 = idx & 15;
                CP_ASYNC16(dE + row * (ES * 2) + c16 * 16,
                           eb + (size_t)row * IBLK + c16 * 8);
            }
            CP_COMMIT();
        }
        bool tr = (jc < I);  // A = stored block transposed
#pragma unroll
        for (int kk2 = 0; kk2 < 8; kk2++) {
            int ka = kk2 * 16;
            uint32_t a0[4], a1[4];
            if (!tr) {
                ldsm_x4(a0, sE + (mbase + (lane & 15)) * (ES * 2)
                                + (ka + ((lane >> 4) << 3)) * 2);
                ldsm_x4(a1, sE + (mbase + 16 + (lane & 15)) * (ES * 2)
                                + (ka + ((lane >> 4) << 3)) * 2);
            } else {
                int erow = ka + (lane & 7) + ((lane & 16) >> 1);
                ldsm_x4_t(a0, sE + erow * (ES * 2) + (mbase + (lane & 8)) * 2);
                ldsm_x4_t(a1, sE + erow * (ES * 2) + (mbase + 16 + (lane & 8)) * 2);
            }
            int jrow = ka + (lane & 7) + (lane & 8);
#pragma unroll
            for (int t2 = 0; t2 < 8; t2++) {
                uint32_t b[4];
                int cc = chalf * 128 + t2 * 16 + ((lane & 16) >> 1);
                ldsm_x4_t(b, sQj + jrow * (QS * 2) + cc * 2);
                mma_bf16(&d2[(2 * t2) * 4],          a0, b[0], b[1]);
                mma_bf16(&d2[(2 * t2 + 1) * 4],      a0, b[2], b[3]);
                mma_bf16(&d2[(16 + 2 * t2) * 4],     a1, b[0], b[1]);
                mma_bf16(&d2[(16 + 2 * t2 + 1) * 4], a1, b[2], b[3]);
            }
        }
        __syncthreads();
    }

    // writeout: D2 partials in bf16
    {
        size_t rb0 = (size_t)split * NPAD + i0 + mbase + (lane >> 2);
#pragma unroll
        for (int mt = 0; mt < 2; mt++) {
            size_t rbase = rb0 + mt * 16;
#pragma unroll
            for (int nn = 0; nn < 16; nn++) {
                int col = chalf * 128 + nn * 8 + ((lane & 3) << 1);
                int idx = (mt * 16 + nn) * 4;
                __nv_bfloat162 p0 = __floats2bfloat162_rn(d2[idx], d2[idx + 1]);
                __nv_bfloat162 p1 = __floats2bfloat162_rn(d2[idx + 2], d2[idx + 3]);
                *(uint32_t*)&g_part[rbase * C2 + col]       = *(uint32_t*)&p0;
                *(uint32_t*)&g_part[(rbase + 8) * C2 + col] = *(uint32_t*)&p1;
            }
        }
    }
}

__global__ void k_invden() {
    int i = blockIdx.x * blockDim.x + threadIdx.x;
    if (i < N_ITEMS) {
        float s = (float)NPAD;  // +1 per j slot (pad slots carry Ec=-1 to cancel)
        for (int sp = 0; sp < NIB; sp++) s += g_denp2[(size_t)sp * NPAD + i];
        g_invden[i] = 1.f / s;
    }
}

// CAT[i] = [emb_item[i] | region[i]],  region = (colsum + sum_splits D2) / den
__global__ void k_cat(const float* __restrict__ emb_item) {
    int gid = blockIdx.x * blockDim.x + threadIdx.x;
    if (gid < N_ITEMS * D3) {
        int i = gid / D3, d = gid % D3;
        float v;
        if (d < DD) {
            v = emb_item[(size_t)i * DD + d];
        } else {
            int c = d - DD;
            float s = g_colsum[c];
#pragma unroll
            for (int sp = 0; sp < RJS; sp++)
                s += __bfloat162float(g_part[((size_t)sp * NPAD + i) * C2 + c]);
            v = s * g_invden[i];
        }
        g_cat[gid] = v;
        g_catb[gid] = __float2bfloat16(v);
    }
}

// ---- bf16 tensor-core GEMM: C[M,384] = A[M,384] @ B[384,384]^T (+ bias) ----
__global__ __launch_bounds__(256) void k_gemm_bf(const __nv_bfloat16* __restrict__ A,
                                                 const __nv_bfloat16* __restrict__ B,
                                                 const float* __restrict__ bias,
                                                 float* __restrict__ C,
                                                 __nv_bfloat16* __restrict__ Cb,
                                                 int M) {
    __shared__ __nv_bfloat16 As[64][72];
    __shared__ __nv_bfloat16 Bs[128][72];
    int tid = threadIdx.x;
    int warp = tid >> 5, lane = tid & 31;
    int bm = blockIdx.x * 64, bn = blockIdx.y * 128;
    const int mrow = (warp >> 1) * 16, nc = (warp & 1) * 64;
    uint32_t sa = smem_to_u32(As), sbb = smem_to_u32(Bs);
    float s[8][4];
#pragma unroll
    for (int t = 0; t < 8; t++)
#pragma unroll
        for (int k = 0; k < 4; k++) s[t][k] = 0.f;

    for (int kt = 0; kt < D3; kt += 64) {
        __syncthreads();
#pragma unroll
        for (int it = 0; it < 2; it++) {
            int idx = it * 256 + tid;
            int row = idx >> 3, c8 = (idx & 7) * 8;
            int gm = bm + row;
            uint4 v = make_uint4(0u, 0u, 0u, 0u);
            if (gm < M) v = *(const uint4*)(A + (size_t)gm * D3 + kt + c8);
            *(uint4*)(&As[row][c8]) = v;
        }
#pragma unroll
        for (int it = 0; it < 4; it++) {
            int idx = it * 256 + tid;
            int row = idx >> 3, c8 = (idx & 7) * 8;
            uint4 v = *(const uint4*)(B + (size_t)(bn + row) * D3 + kt + c8);
            *(uint4*)(&Bs[row][c8]) = v;
        }
        __syncthreads();
#pragma unroll
        for (int kk = 0; kk < 4; kk++) {
            uint32_t a[4];
            ldsm_x4(a, sa + ((mrow + (lane & 15)) * 72 + kk * 16 + ((lane >> 4) << 3)) * 2);
#pragma unroll
            for (int t = 0; t < 4; t++) {
                uint32_t b[4];
                int nrow = nc + t * 16 + (lane & 7) + ((lane & 16) >> 1);
                int bc = kk * 16 + (lane & 8);
                ldsm_x4(b, sbb + (nrow * 72 + bc) * 2);
                mma_bf16(s[2 * t],     a, b[0], b[1]);
                mma_bf16(s[2 * t + 1], a, b[2], b[3]);
            }
        }
    }
    int gm0 = bm + mrow + (lane >> 2);
#pragma unroll
    for (int t = 0; t < 8; t++) {
        int col = bn + nc + t * 8 + ((lane & 3) << 1);
        float b0 = bias ? bias[col] : 0.f;
        float b1 = bias ? bias[col + 1] : 0.f;
        float v00 = s[t][0] + b0, v01 = s[t][1] + b1;
        float v10 = s[t][2] + b0, v11 = s[t][3] + b1;
        if (gm0 < M) {
            if (C) *(float2*)&C[(size_t)gm0 * D3 + col] = make_float2(v00, v01);
            if (Cb) {
                __nv_bfloat162 p = __floats2bfloat162_rn(v00, v01);
                *(uint32_t*)&Cb[(size_t)gm0 * D3 + col] = *(uint32_t*)&p;
            }
        }
        if (gm0 + 8 < M) {
            if (C) *(float2*)&C[(size_t)(gm0 + 8) * D3 + col] = make_float2(v10, v11);
            if (Cb) {
                __nv_bfloat162 p = __floats2bfloat162_rn(v10, v11);
                *(uint32_t*)&Cb[(size_t)(gm0 + 8) * D3 + col] = *(uint32_t*)&p;
            }
        }
    }
}

// ---- split-bf16 GEMM (3 passes: AhBh + AlBh + AhBl), ~fp32 accuracy --------
__global__ __launch_bounds__(256) void k_gemm_bf3(const __nv_bfloat16* __restrict__ Ah,
                                                  const __nv_bfloat16* __restrict__ Al,
                                                  const __nv_bfloat16* __restrict__ Bh,
                                                  const __nv_bfloat16* __restrict__ Bl,
                                                  float* __restrict__ C, int M) {
    __shared__ __nv_bfloat16 As[64][72];
    __shared__ __nv_bfloat16 Bs[128][72];
    int tid = threadIdx.x;
    int warp = tid >> 5, lane = tid & 31;
    int bm = blockIdx.x * 64, bn = blockIdx.y * 128;
    const int mrow = (warp >> 1) * 16, nc = (warp & 1) * 64;
    uint32_t sa = smem_to_u32(As), sbb = smem_to_u32(Bs);
    float s[8][4];
#pragma unroll
    for (int t = 0; t < 8; t++)
#pragma unroll
        for (int k = 0; k < 4; k++) s[t][k] = 0.f;

#pragma unroll
    for (int p = 0; p < 3; p++) {
        const __nv_bfloat16* A = (p == 1) ? Al : Ah;
        const __nv_bfloat16* B = (p == 2) ? Bl : Bh;
        for (int kt = 0; kt < D3; kt += 64) {
            __syncthreads();
#pragma unroll
            for (int it = 0; it < 2; it++) {
                int idx = it * 256 + tid;
                int row = idx >> 3, c8 = (idx & 7) * 8;
                int gm = bm + row;
                uint4 v = make_uint4(0u, 0u, 0u, 0u);
                if (gm < M) v = *(const uint4*)(A + (size_t)gm * D3 + kt + c8);
                *(uint4*)(&As[row][c8]) = v;
            }
#pragma unroll
            for (int it = 0; it < 4; it++) {
                int idx = it * 256 + tid;
                int row = idx >> 3, c8 = (idx & 7) * 8;
                uint4 v = *(const uint4*)(B + (size_t)(bn + row) * D3 + kt + c8);
                *(uint4*)(&Bs[row][c8]) = v;
            }
            __syncthreads();
#pragma unroll
            for (int kk = 0; kk < 4; kk++) {
                uint32_t a[4];
                ldsm_x4(a, sa + ((mrow + (lane & 15)) * 72 + kk * 16 + ((lane >> 4) << 3)) * 2);
#pragma unroll
                for (int t = 0; t < 4; t++) {
                    uint32_t b[4];
                    int nrow = nc + t * 16 + (lane & 7) + ((lane & 16) >> 1);
                    int bc = kk * 16 + (lane & 8);
                    ldsm_x4(b, sbb + (nrow * 72 + bc) * 2);
                    mma_bf16(s[2 * t],     a, b[0], b[1]);
                    mma_bf16(s[2 * t + 1], a, b[2], b[3]);
                }
            }
        }
    }
    int gm0 = bm + mrow + (lane >> 2);
#pragma unroll
    for (int t = 0; t < 8; t++) {
        int col = bn + nc + t * 8 + ((lane & 3) << 1);
        if (gm0 < M)
            *(float2*)&C[(size_t)gm0 * D3 + col] = make_float2(s[t][0], s[t][1]);
        if (gm0 + 8 < M)
            *(float2*)&C[(size_t)(gm0 + 8) * D3 + col] = make_float2(s[t][2], s[t][3]);
    }
}

__global__ void k_tgt(const int* __restrict__ item_i, const int* __restrict__ item_j) {
    int gid = blockIdx.x * blockDim.x + threadIdx.x;
    if (gid < 2 * NBATCH * D3) {
        int row = gid / D3, d = gid % D3;
        int idx = (row < NBATCH) ? item_i[row] : item_j[row - NBATCH];
        float v = g_cat[(size_t)idx * D3 + d];
        g_tgt[gid] = v;
        __nv_bfloat16 hi = __float2bfloat16(v);
        g_tgtb[gid] = hi;
        g_tgtl[gid] = __float2bfloat16(v - __bfloat162float(hi));
    }
}

// per-batch final: shared-row gathers (1 load, 2 FMAs), d-range split across groups
__global__ __launch_bounds__(256) void k_final(const int* __restrict__ user,
                                               const int* __restrict__ item_i,
                                               const float* __restrict__ bv,
                                               float* __restrict__ out) {
    __shared__ int   us[HIST];
    __shared__ float qb[2][D3], ub[2][D3];
    __shared__ float sp_s[2][2][HIST];
    __shared__ float sp_a[2][2][HIST];
    __shared__ float ev[2][HIST], evt[2][HIST];
    __shared__ float bvp[2][8];
    __shared__ float bvd[2];
    int b = blockIdx.x, t = threadIdx.x;
    int lane = t & 31, warp = t >> 5;
    if (t < HIST) us[t] = user[b * HIST + t];
    for (int i = t; i < D3; i += 256) {
        qb[0][i] = g_qp[(size_t)b * D3 + i];
        qb[1][i] = g_qp[(size_t)(NBATCH + b) * D3 + i];
        ub[0][i] = g_uv[(size_t)b * D3 + i];
        ub[1][i] = g_uv[(size_t)(NBATCH + b) * D3 + i];
    }
    {
        float pp = 0.f, pn = 0.f;
        for (int d = t; d < D3; d += 256) {
            float bb = bv[d];
            pp = fmaf(bb, g_tgt[(size_t)b * D3 + d], pp);
            pn = fmaf(bb, g_tgt[(size_t)(NBATCH + b) * D3 + d], pn);
        }
#pragma unroll
        for (int o = 16; o; o >>= 1) {
            pp += __shfl_xor_sync(0xffffffffu, pp, o);
            pn += __shfl_xor_sync(0xffffffffu, pn, o);
        }
        if (lane == 0) { bvp[0][warp] = pp; bvp[1][warp] = pn; }
    }
    __syncthreads();
    if (t < 2) {
        float s = 0.f;
#pragma unroll
        for (int w = 0; w < 8; w++) s += bvp[t][w];
        bvd[t] = s;
    }
    int h = -1, l = 0;
    if (t < HIST) { h = 0; l = t; }
    else if (t >= 128 && t < 128 + HIST) { h = 1; l = t - 128; }
    if (h >= 0) {
        float sp = 0.f, sn = 0.f;
        int r = h ? 50 : 0, cc = l;
        int d = h * 192;
#pragma unroll 4
        for (int i = 0; i < 192; i++) {
            float kev = __bfloat162float(g_keb[(size_t)us[r] * D3 + cc]);
            sp = fmaf(qb[0][d], kev, sp);
            sn = fmaf(qb[1][d], kev, sn);
            d++;
            cc += 100;
            if (cc >= D3) { cc -= D3; r++; }
        }
        sp_s[h][0][l] = sp;
        sp_s[h][1][l] = sn;
        const float* crow = &g_cat[(size_t)us[l] * D3];
        float ap = 0.f, an = 0.f;
        int d0 = h * 192;
#pragma unroll 4
        for (int i = 0; i < 192; i++) {
            float cv = crow[d0 + i];
            ap = fmaf(cv, ub[0][d0 + i], ap);
            an = fmaf(cv, ub[1][d0 + i], an);
        }
        sp_a[h][0][l] = ap;
        sp_a[h][1][l] = an;
    }
    __syncthreads();
    if (t < 2 * HIST) {
        int l2 = t % HIST, br = t / HIST;
        float s = (sp_s[0][br][l2] + sp_s[1][br][l2]) * 0.0510310363f;
        float tv = sp_a[0][br][l2] + sp_a[1][br][l2] + bvd[br];
        float e = expf(s);
        if (br == 0 && us[l2] == item_i[b]) e = 0.f;
        ev[br][l2]  = e;
        evt[br][l2] = e * tv;
    }
    __syncthreads();
    if (t < 2) {
        float se = 0.f, st = 0.f;
        for (int l2 = 0; l2 < HIST; l2++) { se += ev[t][l2]; st += evt[t][l2]; }
        out[(size_t)t * NBATCH + b] = st / sqrtf(se);
    }
}

// ------------- eager preload: module, kernels, local-mem pools --------------
static float* p_cat = nullptr;
static __nv_bfloat16* p_catb = nullptr;
static __nv_bfloat16* p_keb = nullptr;
static float* p_tgt = nullptr;
static __nv_bfloat16* p_tgtb = nullptr;
static __nv_bfloat16* p_tgtl = nullptr;
static float* p_qp  = nullptr;
static float* p_uv  = nullptr;
static __nv_bfloat16* p_wkb = nullptr;
static __nv_bfloat16* p_wqb = nullptr;
static __nv_bfloat16* p_wvh = nullptr;
static __nv_bfloat16* p_wvl = nullptr;
static __nv_bfloat16* p_part = nullptr;
static __nv_bfloat16* p_E = nullptr;

namespace {
struct Preload {
    Preload() {
        cudaFree(0);
        cudaGetSymbolAddress((void**)&p_part, g_part);
        cudaGetSymbolAddress((void**)&p_E, g_E);
        cudaGetSymbolAddress((void**)&p_cat, g_cat);
        cudaGetSymbolAddress((void**)&p_catb, g_catb);
        cudaGetSymbolAddress((void**)&p_keb, g_keb);
        cudaGetSymbolAddress((void**)&p_tgt, g_tgt);
        cudaGetSymbolAddress((void**)&p_tgtb, g_tgtb);
        cudaGetSymbolAddress((void**)&p_tgtl, g_tgtl);
        cudaGetSymbolAddress((void**)&p_qp,  g_qp);
        cudaGetSymbolAddress((void**)&p_uv,  g_uv);
        cudaGetSymbolAddress((void**)&p_wkb, g_wkb);
        cudaGetSymbolAddress((void**)&p_wqb, g_wqb);
        cudaGetSymbolAddress((void**)&p_wvh, g_wvh);
        cudaGetSymbolAddress((void**)&p_wvl, g_wvl);
        cudaFuncAttributes fa;
        cudaFuncGetAttributes(&fa, k_prep);
        cudaFuncGetAttributes(&fa, k_colsum);
        cudaFuncGetAttributes(&fa, k_colred);
        cudaFuncGetAttributes(&fa, k_wprep);
        cudaFuncGetAttributes(&fa, k_scoreA);
        cudaFuncGetAttributes(&fa, k_flashB);
        cudaFuncGetAttributes(&fa, k_invden);
        cudaFuncGetAttributes(&fa, k_cat);
        cudaFuncGetAttributes(&fa, k_gemm_bf);
        cudaFuncGetAttributes(&fa, k_gemm_bf3);
        cudaFuncGetAttributes(&fa, k_tgt);
        cudaFuncGetAttributes(&fa, k_final);
        cudaFuncSetAttribute(k_scoreA, cudaFuncAttributeMaxDynamicSharedMemorySize, SA_TOT);
        cudaFuncSetAttribute(k_flashB, cudaFuncAttributeMaxDynamicSharedMemorySize, SB_TOT);
        cudaMemset(p_part, 0, 8u << 20);
        int*   zints = (int*)p_part;
        float* zf    = (float*)p_part;
        float* fout  = (float*)p_part + (1u << 20);
        k_prep<<<1, 256>>>(zf, zf);
        k_colsum<<<1, 256>>>();
        k_colred<<<1, 256>>>();
        k_wprep<<<1, 256>>>(zf, zf, zf);
        k_scoreA<<<dim3(1, 1), 256, SA_TOT>>>();
        k_flashB<<<dim3(1, 1), 256, SB_TOT>>>();
        k_invden<<<1, 256>>>();
        k_cat<<<1, 256>>>(zf);
        k_gemm_bf<<<dim3(1, 1), 256>>>(p_catb, p_wkb, (const float*)nullptr,
                                       (float*)nullptr, p_keb, 64);
        k_gemm_bf3<<<dim3(1, 1), 256>>>(p_tgtb, p_tgtl, p_wvh, p_wvl, p_uv, 64);
        k_tgt<<<1, 256>>>(zints, zints);
        k_final<<<1, 256>>>(zints, zints, zf, fout);
        cudaDeviceSynchronize();
    }
};
Preload preload_instance_;
}  // namespace

// ---------------------------------------------------------------------------
extern "C" void kernel_launch(void* const* d_in, const int* in_sizes, int n_in,
                              void* d_out, int out_size) {
    const int*   user      = (const int*)d_in[0];
    const int*   item_i    = (const int*)d_in[1];
    const int*   item_j    = (const int*)d_in[2];
    const float* emb_item  = (const float*)d_in[3];
    const float* emb_in    = (const float*)d_in[4];
    const float* emb_out   = (const float*)d_in[5];
    const float* Wq        = (const float*)d_in[6];
    const float* bq        = (const float*)d_in[7];
    const float* Wk        = (const float*)d_in[8];
    const float* bk        = (const float*)d_in[9];
    const float* Wv        = (const float*)d_in[10];
    const float* bv        = (const float*)d_in[11];
    float* out = (float*)d_out;

    k_prep<<<(NPAD * C2 + 255) / 256, 256>>>(emb_in, emb_out);
    k_colsum<<<NCHUNK, 256>>>();
    k_colred<<<1, 256>>>();
    k_wprep<<<(D3 * D3 + 255) / 256, 256>>>(Wk, Wq, Wv);

    // phase A: upper-triangle score blocks (symmetry halves GEMM1)
    k_scoreA<<<dim3(NIB, NIB), 256, SA_TOT>>>();
    // phase B: apply Ec to Q (transposed reads for lower triangle)
    k_flashB<<<dim3(NIB, RJS), 256, SB_TOT>>>();

    k_invden<<<(N_ITEMS + 255) / 256, 256>>>();
    k_cat<<<(N_ITEMS * D3 + 255) / 256, 256>>>(emb_item);

    // KE = CAT @ Wk^T + bk (bf16 TC), bf16 output only (k_final reads keb)
    k_gemm_bf<<<dim3(157, 3), 256>>>(p_catb, p_wkb, bk, (float*)nullptr, p_keb, N_ITEMS);

    k_tgt<<<(2 * NBATCH * D3 + 255) / 256, 256>>>(item_i, item_j);

    // q = TGT @ Wq^T + bq (bf16 TC)
    k_gemm_bf<<<dim3(32, 3), 256>>>(p_tgtb, p_wqb, bq, p_qp,
                                    (__nv_bfloat16*)nullptr, 2 * NBATCH);
    // uv = TGT @ Wv  (split-bf16 TC: AhBh + AlBh + AhBl, ~fp32 accuracy)
    k_gemm_bf3<<<dim3(32, 3), 256>>>(p_tgtb, p_tgtl, p_wvh, p_wvl, p_uv, 2 * NBATCH);

    k_final<<<NBATCH, 256>>>(user, item_i, bv, out);
}

// round 16
// speedup vs baseline: 1.0632x; 1.0632x over previous
#include <cuda_runtime.h>
#include <cuda_bf16.h>
#include <math.h>
#include <stdint.h>

#define N_ITEMS 10000
#define NPAD    10112   // 79 * 128
#define DD      128
#define C2      256
#define D3      384
#define NBATCH  1024
#define HIST    100
#define NCHUNK  79
#define RJS     16
#define CPS     5       // chunks per split (last split gets 4)
#define IBLK    128
#define NIB     79      // NPAD / 128

// SMEM strides (bf16 elements)
#define QS  264         // Qi/Qj row stride (256 + 8 pad), 528B
#define ES  72          // E row stride (64 + 8 pad), 144B

__device__ __forceinline__ uint32_t smem_to_u32(const void* p) {
    uint32_t a;
    asm("{ .reg .u64 t; cvta.to.shared.u64 t, %1; cvt.u32.u64 %0, t; }" : "=r"(a) : "l"(p));
    return a;
}
__device__ __forceinline__ void ldsm_x4(uint32_t r[4], uint32_t addr) {
    asm volatile("ldmatrix.sync.aligned.m8n8.x4.shared.b16 {%0,%1,%2,%3}, [%4];"
                 : "=r"(r[0]), "=r"(r[1]), "=r"(r[2]), "=r"(r[3]) : "r"(addr));
}
__device__ __forceinline__ void ldsm_x4_t(uint32_t r[4], uint32_t addr) {
    asm volatile("ldmatrix.sync.aligned.m8n8.x4.trans.shared.b16 {%0,%1,%2,%3}, [%4];"
                 : "=r"(r[0]), "=r"(r[1]), "=r"(r[2]), "=r"(r[3]) : "r"(addr));
}
__device__ __forceinline__ void mma_bf16(float* c, const uint32_t a[4],
                                         uint32_t b0, uint32_t b1) {
    asm volatile(
        "mma.sync.aligned.m16n8k16.row.col.f32.bf16.bf16.f32 "
        "{%0,%1,%2,%3}, {%4,%5,%6,%7}, {%8,%9}, {%0,%1,%2,%3};"
        : "+f"(c[0]), "+f"(c[1]), "+f"(c[2]), "+f"(c[3])
        : "r"(a[0]), "r"(a[1]), "r"(a[2]), "r"(a[3]), "r"(b0), "r"(b1));
}
#define CP_ASYNC16(dst, src) \
    asm volatile("cp.async.cg.shared.global [%0], [%1], 16;" :: "r"(dst), "l"(src))
#define CP_COMMIT()  asm volatile("cp.async.commit_group;" ::: "memory")
#define CP_WAIT0()   asm volatile("cp.async.wait_group 0;" ::: "memory")
#define STS32(addr, v) \
    asm volatile("st.shared.b32 [%0], %1;" :: "r"(addr), "r"(v) : "memory")
#define NAMED_BAR(id, cnt) \
    asm volatile("bar.sync %0, %1;" :: "r"(id), "r"(cnt) : "memory")

// ---------------- scratch (device globals; loaded eagerly by Preload) ------
__device__ __nv_bfloat16 g_qbf[(size_t)NPAD * C2];
__device__ float g_colpart[NCHUNK][C2];
__device__ float g_colsum[C2];
__device__ __nv_bfloat16 g_part[(size_t)RJS * NPAD * C2];
__device__ float g_denp[RJS * NPAD];
__device__ float g_invden[N_ITEMS];
__device__ float g_cat[(size_t)N_ITEMS * D3];
__device__ __nv_bfloat16 g_catb[(size_t)N_ITEMS * D3];
__device__ __nv_bfloat16 g_keb[(size_t)N_ITEMS * D3];
__device__ float g_tgt[(size_t)2 * NBATCH * D3];
__device__ __nv_bfloat16 g_tgtb[(size_t)2 * NBATCH * D3];
__device__ __nv_bfloat16 g_tgtl[(size_t)2 * NBATCH * D3];
__device__ float g_qp[(size_t)2 * NBATCH * D3];
__device__ float g_uv[(size_t)2 * NBATCH * D3];
__device__ __nv_bfloat16 g_wkb[D3 * D3];
__device__ __nv_bfloat16 g_wqb[D3 * D3];
__device__ __nv_bfloat16 g_wvh[D3 * D3];   // Wv^T hi
__device__ __nv_bfloat16 g_wvl[D3 * D3];   // Wv^T lo

// expm1 for tiny args (|x| ~ 1e-4 here); guarded fallback.
__device__ __forceinline__ float fexpm1(float x) {
    if (fabsf(x) > 0.4f) return __expf(x) - 1.f;
    return x * (1.f + x * (0.5f + x * (0.16666667f + x * 0.04166667f)));
}

// ---------------- prep: bf16 q = [emb_in | emb_out], zero pad rows ----------
__global__ void k_prep(const float* __restrict__ emb_in,
                       const float* __restrict__ emb_out) {
    int gid = blockIdx.x * blockDim.x + threadIdx.x;
    if (gid < NPAD * C2) {
        int i = gid >> 8, c = gid & 255;
        float q = 0.f;
        if (i < N_ITEMS)
            q = (c < DD) ? emb_in[(size_t)i * DD + c] : emb_out[(size_t)i * DD + c - DD];
        g_qbf[gid] = __float2bfloat16(q);
    }
}

__global__ void k_colsum() {
    int b = blockIdx.x, c = threadIdx.x;
    float s = 0.f;
    for (int r = 0; r < 128; r++)
        s += __bfloat162float(g_qbf[(size_t)(b * 128 + r) * C2 + c]);
    g_colpart[b][c] = s;
}
__global__ void k_colred() {
    int c = threadIdx.x;
    float s = 0.f;
    for (int b = 0; b < NCHUNK; b++) s += g_colpart[b][c];
    g_colsum[c] = s;
}

// weights: bf16 Wk, Wq; Wv^T split hi/lo bf16
__global__ void k_wprep(const float* __restrict__ Wk, const float* __restrict__ Wq,
                        const float* __restrict__ Wv) {
    int gid = blockIdx.x * blockDim.x + threadIdx.x;
    if (gid < D3 * D3) {
        g_wkb[gid] = __float2bfloat16(Wk[gid]);
        g_wqb[gid] = __float2bfloat16(Wq[gid]);
        int r = gid / D3, c = gid % D3;
        float v = Wv[gid];
        __nv_bfloat16 hi = __float2bfloat16(v);
        g_wvh[c * D3 + r] = hi;
        g_wvl[c * D3 + r] = __float2bfloat16(v - __bfloat162float(hi));
    }
}

// ---------------- stage A: mma.sync flash, 32-row warp stripes --------------
#define SM_QI   0
#define SM_QJ0  (SM_QI + IBLK * QS * 2)            // 67584
#define SM_QJ1  (SM_QJ0 + 128 * QS * 2)            // +67584
#define SM_E    (SM_QJ1 + 128 * QS * 2)            // 202752
#define SM_DENB (SM_E + IBLK * ES * 2)             // +18432
#define SM_TOT  (SM_DENB + 2 * IBLK * 4)           // 222208

__global__ __launch_bounds__(256, 1) void k_flash() {
    extern __shared__ char smem[];
    uint32_t sb = smem_to_u32(smem);
    const __nv_bfloat16* __restrict__ qg = g_qbf;
    int tid = threadIdx.x;
    int warp = tid >> 5, lane = tid & 31;
    int i0 = blockIdx.x * IBLK;
    int split = blockIdx.y;
    int c0 = split * CPS;
    int c1 = min(NCHUNK, c0 + CPS);
    const int rgrp = warp >> 1, chalf = warp & 1;
    const int mbase = rgrp * 32;

    for (int it = 0; it < 16; it++) {
        int idx = it * 256 + tid;
        int row = idx >> 5, c16 = idx & 31;
        uint4 v = *(const uint4*)(qg + (size_t)(i0 + row) * C2 + (c16 << 3));
        *(uint4*)(smem + SM_QI + row * (QS * 2) + c16 * 16) = v;
    }
    {
        int j0 = c0 * 128;
        for (int it = 0; it < 16; it++) {
            int idx = it * 256 + tid;
            int row = idx >> 5, c16 = idx & 31;
            CP_ASYNC16(sb + SM_QJ0 + row * (QS * 2) + c16 * 16,
                       qg + (size_t)(j0 + row) * C2 + (c16 << 3));
        }
        CP_COMMIT();
    }

    float d2[128];
#pragma unroll
    for (int i = 0; i < 128; i++) d2[i] = 0.f;
    float den[4] = {0.f, 0.f, 0.f, 0.f};

    for (int jc = c0; jc < c1; jc++) {
        int buf = (jc - c0) & 1;
        uint32_t sQj = sb + (buf ? SM_QJ1 : SM_QJ0);
        CP_WAIT0();
        __syncthreads();
        if (jc + 1 < c1) {
            uint32_t dstb = sb + (buf ? SM_QJ0 : SM_QJ1);
            int j0n = (jc + 1) * 128;
            for (int it = 0; it < 16; it++) {
                int idx = it * 256 + tid;
                int row = idx >> 5, c16 = idx & 31;
                CP_ASYNC16(dstb + row * (QS * 2) + c16 * 16,
                           qg + (size_t)(j0n + row) * C2 + (c16 << 3));
            }
            CP_COMMIT();
        }
        int j0 = jc * 128;

#pragma unroll
        for (int hf = 0; hf < 2; hf++) {
            int qb = hf * 64 + chalf * 32;
            float s[8][4];
#pragma unroll
            for (int t = 0; t < 8; t++)
#pragma unroll
                for (int k = 0; k < 4; k++) s[t][k] = 0.f;
#pragma unroll
            for (int kk = 0; kk < 16; kk++) {
                int kc = kk * 16;
                int kcsrc = (128 + kc) & 255;
                uint32_t a0[4], a1[4];
                ldsm_x4(a0, sb + SM_QI + (mbase + (lane & 15)) * (QS * 2)
                                + (kc + ((lane >> 4) << 3)) * 2);
                ldsm_x4(a1, sb + SM_QI + (mbase + 16 + (lane & 15)) * (QS * 2)
                                + (kc + ((lane >> 4) << 3)) * 2);
#pragma unroll
                for (int t = 0; t < 2; t++) {
                    uint32_t b[4];
                    int nrow = qb + t * 16 + (lane & 7) + ((lane & 16) >> 1);
                    int bc = kcsrc + (lane & 8);
                    ldsm_x4(b, sQj + nrow * (QS * 2) + bc * 2);
                    mma_bf16(s[2 * t],         a0, b[0], b[1]);
                    mma_bf16(s[2 * t + 1],     a0, b[2], b[3]);
                    mma_bf16(s[4 + 2 * t],     a1, b[0], b[1]);
                    mma_bf16(s[4 + 2 * t + 1], a1, b[2], b[3]);
                }
            }
#pragma unroll
            for (int st = 0; st < 8; st++) {
                int mt = st >> 2, nt = st & 3;
                int jloc = qb + nt * 8 + ((lane & 3) << 1);
                int jg = j0 + jloc;
                float f0 = (jg     < N_ITEMS) ? fexpm1(s[st][0] * 0.0625f) : -1.f;
                float f1 = (jg + 1 < N_ITEMS) ? fexpm1(s[st][1] * 0.0625f) : -1.f;
                float f2 = (jg     < N_ITEMS) ? fexpm1(s[st][2] * 0.0625f) : -1.f;
                float f3 = (jg + 1 < N_ITEMS) ? fexpm1(s[st][3] * 0.0625f) : -1.f;
                den[mt * 2 + 0] += f0 + f1;
                den[mt * 2 + 1] += f2 + f3;
                __nv_bfloat162 p01 = __floats2bfloat162_rn(f0, f1);
                __nv_bfloat162 p23 = __floats2bfloat162_rn(f2, f3);
                int erow = mbase + mt * 16 + (lane >> 2);
                int ecol = chalf * 32 + nt * 8 + ((lane & 3) << 1);
                STS32(sb + SM_E + erow * (ES * 2) + ecol * 2, *(uint32_t*)&p01);
                STS32(sb + SM_E + (erow + 8) * (ES * 2) + ecol * 2, *(uint32_t*)&p23);
            }
            NAMED_BAR(1 + rgrp, 64);
#pragma unroll
            for (int kk2 = 0; kk2 < 4; kk2++) {
                int ka = kk2 * 16;
                uint32_t a0[4], a1[4];
                ldsm_x4(a0, sb + SM_E + (mbase + (lane & 15)) * (ES * 2)
                                + (ka + ((lane >> 4) << 3)) * 2);
                ldsm_x4(a1, sb + SM_E + (mbase + 16 + (lane & 15)) * (ES * 2)
                                + (ka + ((lane >> 4) << 3)) * 2);
                int jrow = hf * 64 + ka + (lane & 7) + (lane & 8);
#pragma unroll
                for (int t2 = 0; t2 < 8; t2++) {
                    uint32_t b[4];
                    int cc = chalf * 128 + t2 * 16 + ((lane & 16) >> 1);
                    ldsm_x4_t(b, sQj + jrow * (QS * 2) + cc * 2);
                    mma_bf16(&d2[(2 * t2) * 4],          a0, b[0], b[1]);
                    mma_bf16(&d2[(2 * t2 + 1) * 4],      a0, b[2], b[3]);
                    mma_bf16(&d2[(16 + 2 * t2) * 4],     a1, b[0], b[1]);
                    mma_bf16(&d2[(16 + 2 * t2 + 1) * 4], a1, b[2], b[3]);
                }
            }
            NAMED_BAR(1 + rgrp, 64);
        }
    }

    // ---- writeout: D2 partials in bf16 -------------------------------------
    {
        size_t rb0 = (size_t)split * NPAD + i0 + mbase + (lane >> 2);
#pragma unroll
        for (int mt = 0; mt < 2; mt++) {
            size_t rbase = rb0 + mt * 16;
#pragma unroll
            for (int nn = 0; nn < 16; nn++) {
                int col = chalf * 128 + nn * 8 + ((lane & 3) << 1);
                int idx = (mt * 16 + nn) * 4;
                __nv_bfloat162 p0 = __floats2bfloat162_rn(d2[idx], d2[idx + 1]);
                __nv_bfloat162 p1 = __floats2bfloat162_rn(d2[idx + 2], d2[idx + 3]);
                *(uint32_t*)&g_part[rbase * C2 + col]       = *(uint32_t*)&p0;
                *(uint32_t*)&g_part[(rbase + 8) * C2 + col] = *(uint32_t*)&p1;
            }
        }
    }
#pragma unroll
    for (int q = 0; q < 4; q++) {
        den[q] += __shfl_xor_sync(0xffffffffu, den[q], 1);
        den[q] += __shfl_xor_sync(0xffffffffu, den[q], 2);
    }
    if ((lane & 3) == 0) {
        float* db = (float*)(smem + SM_DENB) + chalf * IBLK;
#pragma unroll
        for (int mt = 0; mt < 2; mt++) {
            db[mbase + mt * 16 + (lane >> 2)]     = den[mt * 2 + 0];
            db[mbase + mt * 16 + 8 + (lane >> 2)] = den[mt * 2 + 1];
        }
    }
    __syncthreads();
    if (tid < IBLK) {
        const float* db = (const float*)(smem + SM_DENB);
        g_denp[split * NPAD + i0 + tid] = db[tid] + db[IBLK + tid];
    }
}

__global__ void k_invden() {
    int i = blockIdx.x * blockDim.x + threadIdx.x;
    if (i < N_ITEMS) {
        float s = (float)NPAD;
#pragma unroll
        for (int sp = 0; sp < RJS; sp++) s += g_denp[sp * NPAD + i];
        g_invden[i] = 1.f / s;
    }
}

// CAT[i] = [emb_item[i] | region[i]],  region = (colsum + sum_splits D2) / den
__global__ void k_cat(const float* __restrict__ emb_item) {
    int gid = blockIdx.x * blockDim.x + threadIdx.x;
    if (gid < N_ITEMS * D3) {
        int i = gid / D3, d = gid % D3;
        float v;
        if (d < DD) {
            v = emb_item[(size_t)i * DD + d];
        } else {
            int c = d - DD;
            float s = g_colsum[c];
#pragma unroll
            for (int sp = 0; sp < RJS; sp++)
                s += __bfloat162float(g_part[((size_t)sp * NPAD + i) * C2 + c]);
            v = s * g_invden[i];
        }
        g_cat[gid] = v;
        g_catb[gid] = __float2bfloat16(v);
    }
}

// ---- shared GEMM tile body (device function) -------------------------------
__device__ __forceinline__ void gemm_pass(const __nv_bfloat16* __restrict__ A,
                                          const __nv_bfloat16* __restrict__ B,
                                          float s[8][4],
                                          __nv_bfloat16 (*As)[72],
                                          __nv_bfloat16 (*Bs)[72],
                                          uint32_t sa, uint32_t sbb,
                                          int bm, int bn, int M,
                                          int tid, int warp, int lane,
                                          int mrow, int nc) {
    for (int kt = 0; kt < D3; kt += 64) {
        __syncthreads();
#pragma unroll
        for (int it = 0; it < 2; it++) {
            int idx = it * 256 + tid;
            int row = idx >> 3, c8 = (idx & 7) * 8;
            int gm = bm + row;
            uint4 v = make_uint4(0u, 0u, 0u, 0u);
            if (gm < M) v = *(const uint4*)(A + (size_t)gm * D3 + kt + c8);
            *(uint4*)(&As[row][c8]) = v;
        }
#pragma unroll
        for (int it = 0; it < 4; it++) {
            int idx = it * 256 + tid;
            int row = idx >> 3, c8 = (idx & 7) * 8;
            uint4 v = *(const uint4*)(B + (size_t)(bn + row) * D3 + kt + c8);
            *(uint4*)(&Bs[row][c8]) = v;
        }
        __syncthreads();
#pragma unroll
        for (int kk = 0; kk < 4; kk++) {
            uint32_t a[4];
            ldsm_x4(a, sa + ((mrow + (lane & 15)) * 72 + kk * 16 + ((lane >> 4) << 3)) * 2);
#pragma unroll
            for (int t = 0; t < 4; t++) {
                uint32_t b[4];
                int nrow = nc + t * 16 + (lane & 7) + ((lane & 16) >> 1);
                int bc = kk * 16 + (lane & 8);
                ldsm_x4(b, sbb + (nrow * 72 + bc) * 2);
                mma_bf16(s[2 * t],     a, b[0], b[1]);
                mma_bf16(s[2 * t + 1], a, b[2], b[3]);
            }
        }
    }
}

// ---- bf16 tensor-core GEMM: C[M,384] = A[M,384] @ B[384,384]^T (+ bias) ----
__global__ __launch_bounds__(256) void k_gemm_bf(const __nv_bfloat16* __restrict__ A,
                                                 const __nv_bfloat16* __restrict__ B,
                                                 const float* __restrict__ bias,
                                                 float* __restrict__ C,
                                                 __nv_bfloat16* __restrict__ Cb,
                                                 int M) {
    __shared__ __nv_bfloat16 As[64][72];
    __shared__ __nv_bfloat16 Bs[128][72];
    int tid = threadIdx.x;
    int warp = tid >> 5, lane = tid & 31;
    int bm = blockIdx.x * 64, bn = blockIdx.y * 128;
    const int mrow = (warp >> 1) * 16, nc = (warp & 1) * 64;
    uint32_t sa = smem_to_u32(As), sbb = smem_to_u32(Bs);
    float s[8][4];
#pragma unroll
    for (int t = 0; t < 8; t++)
#pragma unroll
        for (int k = 0; k < 4; k++) s[t][k] = 0.f;

    gemm_pass(A, B, s, As, Bs, sa, sbb, bm, bn, M, tid, warp, lane, mrow, nc);

    int gm0 = bm + mrow + (lane >> 2);
#pragma unroll
    for (int t = 0; t < 8; t++) {
        int col = bn + nc + t * 8 + ((lane & 3) << 1);
        float b0 = bias ? bias[col] : 0.f;
        float b1 = bias ? bias[col + 1] : 0.f;
        float v00 = s[t][0] + b0, v01 = s[t][1] + b1;
        float v10 = s[t][2] + b0, v11 = s[t][3] + b1;
        if (gm0 < M) {
            if (C) *(float2*)&C[(size_t)gm0 * D3 + col] = make_float2(v00, v01);
            if (Cb) {
                __nv_bfloat162 p = __floats2bfloat162_rn(v00, v01);
                *(uint32_t*)&Cb[(size_t)gm0 * D3 + col] = *(uint32_t*)&p;
            }
        }
        if (gm0 + 8 < M) {
            if (C) *(float2*)&C[(size_t)(gm0 + 8) * D3 + col] = make_float2(v10, v11);
            if (Cb) {
                __nv_bfloat162 p = __floats2bfloat162_rn(v10, v11);
                *(uint32_t*)&Cb[(size_t)(gm0 + 8) * D3 + col] = *(uint32_t*)&p;
            }
        }
    }
}

// ---- merged tgt GEMMs: z=0 -> qp (1 pass + bias); z=1 -> uv (split-bf16 x3)
__global__ __launch_bounds__(256) void k_gemm_tgt(const __nv_bfloat16* __restrict__ Ah,
                                                  const __nv_bfloat16* __restrict__ Al,
                                                  const __nv_bfloat16* __restrict__ Wq,
                                                  const float* __restrict__ bq,
                                                  float* __restrict__ Cqp,
                                                  const __nv_bfloat16* __restrict__ Bh,
                                                  const __nv_bfloat16* __restrict__ Bl,
                                                  float* __restrict__ Cuv, int M) {
    __shared__ __nv_bfloat16 As[64][72];
    __shared__ __nv_bfloat16 Bs[128][72];
    int tid = threadIdx.x;
    int warp = tid >> 5, lane = tid & 31;
    int bm = blockIdx.x * 64, bn = blockIdx.y * 128;
    const int mrow = (warp >> 1) * 16, nc = (warp & 1) * 64;
    uint32_t sa = smem_to_u32(As), sbb = smem_to_u32(Bs);
    float s[8][4];
#pragma unroll
    for (int t = 0; t < 8; t++)
#pragma unroll
        for (int k = 0; k < 4; k++) s[t][k] = 0.f;

    int gm0 = bm + mrow + (lane >> 2);
    if (blockIdx.z == 0) {
        // qp = TGT @ Wq^T + bq (single bf16 pass)
        gemm_pass(Ah, Wq, s, As, Bs, sa, sbb, bm, bn, M, tid, warp, lane, mrow, nc);
#pragma unroll
        for (int t = 0; t < 8; t++) {
            int col = bn + nc + t * 8 + ((lane & 3) << 1);
            float b0 = bq[col], b1 = bq[col + 1];
            if (gm0 < M)
                *(float2*)&Cqp[(size_t)gm0 * D3 + col] =
                    make_float2(s[t][0] + b0, s[t][1] + b1);
            if (gm0 + 8 < M)
                *(float2*)&Cqp[(size_t)(gm0 + 8) * D3 + col] =
                    make_float2(s[t][2] + b0, s[t][3] + b1);
        }
    } else {
        // uv = TGT @ Wv (split-bf16: AhBh + AlBh + AhBl)
        gemm_pass(Ah, Bh, s, As, Bs, sa, sbb, bm, bn, M, tid, warp, lane, mrow, nc);
        gemm_pass(Al, Bh, s, As, Bs, sa, sbb, bm, bn, M, tid, warp, lane, mrow, nc);
        gemm_pass(Ah, Bl, s, As, Bs, sa, sbb, bm, bn, M, tid, warp, lane, mrow, nc);
#pragma unroll
        for (int t = 0; t < 8; t++) {
            int col = bn + nc + t * 8 + ((lane & 3) << 1);
            if (gm0 < M)
                *(float2*)&Cuv[(size_t)gm0 * D3 + col] = make_float2(s[t][0], s[t][1]);
            if (gm0 + 8 < M)
                *(float2*)&Cuv[(size_t)(gm0 + 8) * D3 + col] = make_float2(s[t][2], s[t][3]);
        }
    }
}

__global__ void k_tgt(const int* __restrict__ item_i, const int* __restrict__ item_j) {
    int gid = blockIdx.x * blockDim.x + threadIdx.x;
    if (gid < 2 * NBATCH * D3) {
        int row = gid / D3, d = gid % D3;
        int idx = (row < NBATCH) ? item_i[row] : item_j[row - NBATCH];
        float v = g_cat[(size_t)idx * D3 + d];
        g_tgt[gid] = v;
        __nv_bfloat16 hi = __float2bfloat16(v);
        g_tgtb[gid] = hi;
        g_tgtl[gid] = __float2bfloat16(v - __bfloat162float(hi));
    }
}

// per-batch final: shared-row gathers (1 load, 2 FMAs), d-range split across groups
__global__ __launch_bounds__(256) void k_final(const int* __restrict__ user,
                                               const int* __restrict__ item_i,
                                               const float* __restrict__ bv,
                                               float* __restrict__ out) {
    __shared__ int   us[HIST];
    __shared__ float qb[2][D3], ub[2][D3];
    __shared__ float sp_s[2][2][HIST];
    __shared__ float sp_a[2][2][HIST];
    __shared__ float ev[2][HIST], evt[2][HIST];
    __shared__ float bvp[2][8];
    __shared__ float bvd[2];
    int b = blockIdx.x, t = threadIdx.x;
    int lane = t & 31, warp = t >> 5;
    if (t < HIST) us[t] = user[b * HIST + t];
    for (int i = t; i < D3; i += 256) {
        qb[0][i] = g_qp[(size_t)b * D3 + i];
        qb[1][i] = g_qp[(size_t)(NBATCH + b) * D3 + i];
        ub[0][i] = g_uv[(size_t)b * D3 + i];
        ub[1][i] = g_uv[(size_t)(NBATCH + b) * D3 + i];
    }
    {
        float pp = 0.f, pn = 0.f;
        for (int d = t; d < D3; d += 256) {
            float bb = bv[d];
            pp = fmaf(bb, g_tgt[(size_t)b * D3 + d], pp);
            pn = fmaf(bb, g_tgt[(size_t)(NBATCH + b) * D3 + d], pn);
        }
#pragma unroll
        for (int o = 16; o; o >>= 1) {
            pp += __shfl_xor_sync(0xffffffffu, pp, o);
            pn += __shfl_xor_sync(0xffffffffu, pn, o);
        }
        if (lane == 0) { bvp[0][warp] = pp; bvp[1][warp] = pn; }
    }
    __syncthreads();
    if (t < 2) {
        float s = 0.f;
#pragma unroll
        for (int w = 0; w < 8; w++) s += bvp[t][w];
        bvd[t] = s;
    }
    int h = -1, l = 0;
    if (t < HIST) { h = 0; l = t; }
    else if (t >= 128 && t < 128 + HIST) { h = 1; l = t - 128; }
    if (h >= 0) {
        float sp = 0.f, sn = 0.f;
        int r = h ? 50 : 0, cc = l;
        int d = h * 192;
#pragma unroll 4
        for (int i = 0; i < 192; i++) {
            float kev = __bfloat162float(g_keb[(size_t)us[r] * D3 + cc]);
            sp = fmaf(qb[0][d], kev, sp);
            sn = fmaf(qb[1][d], kev, sn);
            d++;
            cc += 100;
            if (cc >= D3) { cc -= D3; r++; }
        }
        sp_s[h][0][l] = sp;
        sp_s[h][1][l] = sn;
        const float* crow = &g_cat[(size_t)us[l] * D3];
        float ap = 0.f, an = 0.f;
        int d0 = h * 192;
#pragma unroll 4
        for (int i = 0; i < 192; i++) {
            float cv = crow[d0 + i];
            ap = fmaf(cv, ub[0][d0 + i], ap);
            an = fmaf(cv, ub[1][d0 + i], an);
        }
        sp_a[h][0][l] = ap;
        sp_a[h][1][l] = an;
    }
    __syncthreads();
    if (t < 2 * HIST) {
        int l2 = t % HIST, br = t / HIST;
        float s = (sp_s[0][br][l2] + sp_s[1][br][l2]) * 0.0510310363f;
        float tv = sp_a[0][br][l2] + sp_a[1][br][l2] + bvd[br];
        float e = expf(s);
        if (br == 0 && us[l2] == item_i[b]) e = 0.f;
        ev[br][l2]  = e;
        evt[br][l2] = e * tv;
    }
    __syncthreads();
    if (t < 2) {
        float se = 0.f, st = 0.f;
        for (int l2 = 0; l2 < HIST; l2++) { se += ev[t][l2]; st += evt[t][l2]; }
        out[(size_t)t * NBATCH + b] = st / sqrtf(se);
    }
}

// ------------- eager preload: module, kernels, local-mem pools --------------
static float* p_cat = nullptr;
static __nv_bfloat16* p_catb = nullptr;
static __nv_bfloat16* p_keb = nullptr;
static float* p_tgt = nullptr;
static __nv_bfloat16* p_tgtb = nullptr;
static __nv_bfloat16* p_tgtl = nullptr;
static float* p_qp  = nullptr;
static float* p_uv  = nullptr;
static __nv_bfloat16* p_wkb = nullptr;
static __nv_bfloat16* p_wqb = nullptr;
static __nv_bfloat16* p_wvh = nullptr;
static __nv_bfloat16* p_wvl = nullptr;
static __nv_bfloat16* p_part = nullptr;

namespace {
struct Preload {
    Preload() {
        cudaFree(0);
        cudaGetSymbolAddress((void**)&p_part, g_part);
        cudaGetSymbolAddress((void**)&p_cat, g_cat);
        cudaGetSymbolAddress((void**)&p_catb, g_catb);
        cudaGetSymbolAddress((void**)&p_keb, g_keb);
        cudaGetSymbolAddress((void**)&p_tgt, g_tgt);
        cudaGetSymbolAddress((void**)&p_tgtb, g_tgtb);
        cudaGetSymbolAddress((void**)&p_tgtl, g_tgtl);
        cudaGetSymbolAddress((void**)&p_qp,  g_qp);
        cudaGetSymbolAddress((void**)&p_uv,  g_uv);
        cudaGetSymbolAddress((void**)&p_wkb, g_wkb);
        cudaGetSymbolAddress((void**)&p_wqb, g_wqb);
        cudaGetSymbolAddress((void**)&p_wvh, g_wvh);
        cudaGetSymbolAddress((void**)&p_wvl, g_wvl);
        cudaFuncAttributes fa;
        cudaFuncGetAttributes(&fa, k_prep);
        cudaFuncGetAttributes(&fa, k_colsum);
        cudaFuncGetAttributes(&fa, k_colred);
        cudaFuncGetAttributes(&fa, k_wprep);
        cudaFuncGetAttributes(&fa, k_flash);
        cudaFuncGetAttributes(&fa, k_invden);
        cudaFuncGetAttributes(&fa, k_cat);
        cudaFuncGetAttributes(&fa, k_gemm_bf);
        cudaFuncGetAttributes(&fa, k_gemm_tgt);
        cudaFuncGetAttributes(&fa, k_tgt);
        cudaFuncGetAttributes(&fa, k_final);
        cudaFuncSetAttribute(k_flash, cudaFuncAttributeMaxDynamicSharedMemorySize, SM_TOT);
        cudaMemset(p_part, 0, 8u << 20);
        int*   zints = (int*)p_part;
        float* zf    = (float*)p_part;
        float* fout  = (float*)p_part + (1u << 20);
        k_prep<<<1, 256>>>(zf, zf);
        k_colsum<<<1, 256>>>();
        k_colred<<<1, 256>>>();
        k_wprep<<<1, 256>>>(zf, zf, zf);
        k_flash<<<dim3(1, 1), 256, SM_TOT>>>();
        k_invden<<<1, 256>>>();
        k_cat<<<1, 256>>>(zf);
        k_gemm_bf<<<dim3(1, 1), 256>>>(p_catb, p_wkb, (const float*)nullptr,
                                       (float*)nullptr, p_keb, 64);
        k_gemm_tgt<<<dim3(1, 1, 2), 256>>>(p_tgtb, p_tgtl, p_wqb, zf, p_qp,
                                           p_wvh, p_wvl, p_uv, 64);
        k_tgt<<<1, 256>>>(zints, zints);
        k_final<<<1, 256>>>(zints, zints, zf, fout);
        cudaDeviceSynchronize();
    }
};
Preload preload_instance_;
}  // namespace

// ---------------------------------------------------------------------------
extern "C" void kernel_launch(void* const* d_in, const int* in_sizes, int n_in,
                              void* d_out, int out_size) {
    const int*   user      = (const int*)d_in[0];
    const int*   item_i    = (const int*)d_in[1];
    const int*   item_j    = (const int*)d_in[2];
    const float* emb_item  = (const float*)d_in[3];
    const float* emb_in    = (const float*)d_in[4];
    const float* emb_out   = (const float*)d_in[5];
    const float* Wq        = (const float*)d_in[6];
    const float* bq        = (const float*)d_in[7];
    const float* Wk        = (const float*)d_in[8];
    const float* bk        = (const float*)d_in[9];
    const float* Wv        = (const float*)d_in[10];
    const float* bv        = (const float*)d_in[11];
    float* out = (float*)d_out;

    k_prep<<<(NPAD * C2 + 255) / 256, 256>>>(emb_in, emb_out);
    k_colsum<<<NCHUNK, 256>>>();
    k_colred<<<1, 256>>>();
    k_wprep<<<(D3 * D3 + 255) / 256, 256>>>(Wk, Wq, Wv);

    k_flash<<<dim3(NIB, RJS), 256, SM_TOT>>>();

    k_invden<<<(N_ITEMS + 255) / 256, 256>>>();
    k_cat<<<(N_ITEMS * D3 + 255) / 256, 256>>>(emb_item);

    // KE = CAT @ Wk^T + bk (bf16 TC), bf16 output only (k_final reads keb)
    k_gemm_bf<<<dim3(157, 3), 256>>>(p_catb, p_wkb, bk, (float*)nullptr, p_keb, N_ITEMS);

    k_tgt<<<(2 * NBATCH * D3 + 255) / 256, 256>>>(item_i, item_j);

    // merged: z=0 -> qp = TGT@Wq^T+bq; z=1 -> uv = TGT@Wv (split-bf16)
    k_gemm_tgt<<<dim3(32, 3, 2), 256>>>(p_tgtb, p_tgtl, p_wqb, bq, p_qp,
                                        p_wvh, p_wvl, p_uv, 2 * NBATCH);

    k_final<<<NBATCH, 256>>>(user, item_i, bv, out);
}

// round 17
// speedup vs baseline: 1.1083x; 1.0423x over previous
#include <cuda_runtime.h>
#include <cuda_bf16.h>
#include <math.h>
#include <stdint.h>

#define N_ITEMS 10000
#define NPAD    10112   // 79 * 128
#define DD      128
#define C2      256
#define D3      384
#define NBATCH  1024
#define HIST    100
#define NCHUNK  79
#define RJS     16
#define CPS     5       // chunks per split (last split gets 4)
#define IBLK    128
#define NIB     79      // NPAD / 128

// SMEM strides (bf16 elements)
#define QS  264         // Qi/Qj row stride (256 + 8 pad), 528B
#define ES  72          // E row stride (64 + 8 pad), 144B

__device__ __forceinline__ uint32_t smem_to_u32(const void* p) {
    uint32_t a;
    asm("{ .reg .u64 t; cvta.to.shared.u64 t, %1; cvt.u32.u64 %0, t; }" : "=r"(a) : "l"(p));
    return a;
}
__device__ __forceinline__ void ldsm_x4(uint32_t r[4], uint32_t addr) {
    asm volatile("ldmatrix.sync.aligned.m8n8.x4.shared.b16 {%0,%1,%2,%3}, [%4];"
                 : "=r"(r[0]), "=r"(r[1]), "=r"(r[2]), "=r"(r[3]) : "r"(addr));
}
__device__ __forceinline__ void ldsm_x4_t(uint32_t r[4], uint32_t addr) {
    asm volatile("ldmatrix.sync.aligned.m8n8.x4.trans.shared.b16 {%0,%1,%2,%3}, [%4];"
                 : "=r"(r[0]), "=r"(r[1]), "=r"(r[2]), "=r"(r[3]) : "r"(addr));
}
__device__ __forceinline__ void mma_bf16(float* c, const uint32_t a[4],
                                         uint32_t b0, uint32_t b1) {
    asm volatile(
        "mma.sync.aligned.m16n8k16.row.col.f32.bf16.bf16.f32 "
        "{%0,%1,%2,%3}, {%4,%5,%6,%7}, {%8,%9}, {%0,%1,%2,%3};"
        : "+f"(c[0]), "+f"(c[1]), "+f"(c[2]), "+f"(c[3])
        : "r"(a[0]), "r"(a[1]), "r"(a[2]), "r"(a[3]), "r"(b0), "r"(b1));
}
#define CP_ASYNC16(dst, src) \
    asm volatile("cp.async.cg.shared.global [%0], [%1], 16;" :: "r"(dst), "l"(src))
#define CP_COMMIT()  asm volatile("cp.async.commit_group;" ::: "memory")
#define CP_WAIT0()   asm volatile("cp.async.wait_group 0;" ::: "memory")
#define STS32(addr, v) \
    asm volatile("st.shared.b32 [%0], %1;" :: "r"(addr), "r"(v) : "memory")
#define NAMED_BAR(id, cnt) \
    asm volatile("bar.sync %0, %1;" :: "r"(id), "r"(cnt) : "memory")

// ---------------- scratch (device globals; loaded eagerly by Preload) ------
__device__ __nv_bfloat16 g_qbf[(size_t)NPAD * C2];
__device__ float g_colpart[NCHUNK][C2];
__device__ float g_colsum[C2];
__device__ __nv_bfloat16 g_part[(size_t)RJS * NPAD * C2];
__device__ float g_denp[RJS * NPAD];
__device__ float g_invden[N_ITEMS];
__device__ float g_cat[(size_t)N_ITEMS * D3];
__device__ __nv_bfloat16 g_catb[(size_t)N_ITEMS * D3];
__device__ __nv_bfloat16 g_keb[(size_t)N_ITEMS * D3];
__device__ float g_tgt[(size_t)2 * NBATCH * D3];
__device__ __nv_bfloat16 g_tgtb[(size_t)2 * NBATCH * D3];
__device__ __nv_bfloat16 g_tgtl[(size_t)2 * NBATCH * D3];
__device__ float g_qp[(size_t)2 * NBATCH * D3];
__device__ float g_uv[(size_t)2 * NBATCH * D3];
__device__ __nv_bfloat16 g_wkb[D3 * D3];
__device__ __nv_bfloat16 g_wqb[D3 * D3];
__device__ __nv_bfloat16 g_wvh[D3 * D3];   // Wv^T hi
__device__ __nv_bfloat16 g_wvl[D3 * D3];   // Wv^T lo

// expm1 for tiny args (|x| ~ 1e-4 here); guarded fallback.
__device__ __forceinline__ float fexpm1(float x) {
    if (fabsf(x) > 0.4f) return __expf(x) - 1.f;
    return x * (1.f + x * (0.5f + x * (0.16666667f + x * 0.04166667f)));
}

// ---------------- prep: bf16 q = [emb_in | emb_out], zero pad rows ----------
__global__ void k_prep(const float* __restrict__ emb_in,
                       const float* __restrict__ emb_out) {
    int gid = blockIdx.x * blockDim.x + threadIdx.x;
    if (gid < NPAD * C2) {
        int i = gid >> 8, c = gid & 255;
        float q = 0.f;
        if (i < N_ITEMS)
            q = (c < DD) ? emb_in[(size_t)i * DD + c] : emb_out[(size_t)i * DD + c - DD];
        g_qbf[gid] = __float2bfloat16(q);
    }
}

__global__ void k_colsum() {
    int b = blockIdx.x, c = threadIdx.x;
    float s = 0.f;
    for (int r = 0; r < 128; r++)
        s += __bfloat162float(g_qbf[(size_t)(b * 128 + r) * C2 + c]);
    g_colpart[b][c] = s;
}
__global__ void k_colred() {
    int c = threadIdx.x;
    float s = 0.f;
    for (int b = 0; b < NCHUNK; b++) s += g_colpart[b][c];
    g_colsum[c] = s;
}

// weights: bf16 Wk, Wq; Wv^T split hi/lo bf16
__global__ void k_wprep(const float* __restrict__ Wk, const float* __restrict__ Wq,
                        const float* __restrict__ Wv) {
    int gid = blockIdx.x * blockDim.x + threadIdx.x;
    if (gid < D3 * D3) {
        g_wkb[gid] = __float2bfloat16(Wk[gid]);
        g_wqb[gid] = __float2bfloat16(Wq[gid]);
        int r = gid / D3, c = gid % D3;
        float v = Wv[gid];
        __nv_bfloat16 hi = __float2bfloat16(v);
        g_wvh[c * D3 + r] = hi;
        g_wvl[c * D3 + r] = __float2bfloat16(v - __bfloat162float(hi));
    }
}

// ---------------- stage A: mma.sync flash, 32-row warp stripes --------------
#define SM_QI   0
#define SM_QJ0  (SM_QI + IBLK * QS * 2)            // 67584
#define SM_QJ1  (SM_QJ0 + 128 * QS * 2)            // +67584
#define SM_E    (SM_QJ1 + 128 * QS * 2)            // 202752
#define SM_DENB (SM_E + IBLK * ES * 2)             // +18432
#define SM_TOT  (SM_DENB + 2 * IBLK * 4)           // 222208

__global__ __launch_bounds__(256, 1) void k_flash() {
    extern __shared__ char smem[];
    uint32_t sb = smem_to_u32(smem);
    const __nv_bfloat16* __restrict__ qg = g_qbf;
    int tid = threadIdx.x;
    int warp = tid >> 5, lane = tid & 31;
    int i0 = blockIdx.x * IBLK;
    int split = blockIdx.y;
    int c0 = split * CPS;
    int c1 = min(NCHUNK, c0 + CPS);
    const int rgrp = warp >> 1, chalf = warp & 1;
    const int mbase = rgrp * 32;

    for (int it = 0; it < 16; it++) {
        int idx = it * 256 + tid;
        int row = idx >> 5, c16 = idx & 31;
        uint4 v = *(const uint4*)(qg + (size_t)(i0 + row) * C2 + (c16 << 3));
        *(uint4*)(smem + SM_QI + row * (QS * 2) + c16 * 16) = v;
    }
    {
        int j0 = c0 * 128;
        for (int it = 0; it < 16; it++) {
            int idx = it * 256 + tid;
            int row = idx >> 5, c16 = idx & 31;
            CP_ASYNC16(sb + SM_QJ0 + row * (QS * 2) + c16 * 16,
                       qg + (size_t)(j0 + row) * C2 + (c16 << 3));
        }
        CP_COMMIT();
    }

    float d2[128];
#pragma unroll
    for (int i = 0; i < 128; i++) d2[i] = 0.f;
    float den[4] = {0.f, 0.f, 0.f, 0.f};

    for (int jc = c0; jc < c1; jc++) {
        int buf = (jc - c0) & 1;
        uint32_t sQj = sb + (buf ? SM_QJ1 : SM_QJ0);
        CP_WAIT0();
        __syncthreads();
        if (jc + 1 < c1) {
            uint32_t dstb = sb + (buf ? SM_QJ0 : SM_QJ1);
            int j0n = (jc + 1) * 128;
            for (int it = 0; it < 16; it++) {
                int idx = it * 256 + tid;
                int row = idx >> 5, c16 = idx & 31;
                CP_ASYNC16(dstb + row * (QS * 2) + c16 * 16,
                           qg + (size_t)(j0n + row) * C2 + (c16 << 3));
            }
            CP_COMMIT();
        }
        int j0 = jc * 128;

#pragma unroll
        for (int hf = 0; hf < 2; hf++) {
            int qb = hf * 64 + chalf * 32;
            float s[8][4];
#pragma unroll
            for (int t = 0; t < 8; t++)
#pragma unroll
                for (int k = 0; k < 4; k++) s[t][k] = 0.f;
#pragma unroll
            for (int kk = 0; kk < 16; kk++) {
                int kc = kk * 16;
                int kcsrc = (128 + kc) & 255;
                uint32_t a0[4], a1[4];
                ldsm_x4(a0, sb + SM_QI + (mbase + (lane & 15)) * (QS * 2)
                                + (kc + ((lane >> 4) << 3)) * 2);
                ldsm_x4(a1, sb + SM_QI + (mbase + 16 + (lane & 15)) * (QS * 2)
                                + (kc + ((lane >> 4) << 3)) * 2);
#pragma unroll
                for (int t = 0; t < 2; t++) {
                    uint32_t b[4];
                    int nrow = qb + t * 16 + (lane & 7) + ((lane & 16) >> 1);
                    int bc = kcsrc + (lane & 8);
                    ldsm_x4(b, sQj + nrow * (QS * 2) + bc * 2);
                    mma_bf16(s[2 * t],         a0, b[0], b[1]);
                    mma_bf16(s[2 * t + 1],     a0, b[2], b[3]);
                    mma_bf16(s[4 + 2 * t],     a1, b[0], b[1]);
                    mma_bf16(s[4 + 2 * t + 1], a1, b[2], b[3]);
                }
            }
#pragma unroll
            for (int st = 0; st < 8; st++) {
                int mt = st >> 2, nt = st & 3;
                int jloc = qb + nt * 8 + ((lane & 3) << 1);
                int jg = j0 + jloc;
                float f0 = (jg     < N_ITEMS) ? fexpm1(s[st][0] * 0.0625f) : -1.f;
                float f1 = (jg + 1 < N_ITEMS) ? fexpm1(s[st][1] * 0.0625f) : -1.f;
                float f2 = (jg     < N_ITEMS) ? fexpm1(s[st][2] * 0.0625f) : -1.f;
                float f3 = (jg + 1 < N_ITEMS) ? fexpm1(s[st][3] * 0.0625f) : -1.f;
                den[mt * 2 + 0] += f0 + f1;
                den[mt * 2 + 1] += f2 + f3;
                __nv_bfloat162 p01 = __floats2bfloat162_rn(f0, f1);
                __nv_bfloat162 p23 = __floats2bfloat162_rn(f2, f3);
                int erow = mbase + mt * 16 + (lane >> 2);
                int ecol = chalf * 32 + nt * 8 + ((lane & 3) << 1);
                STS32(sb + SM_E + erow * (ES * 2) + ecol * 2, *(uint32_t*)&p01);
                STS32(sb + SM_E + (erow + 8) * (ES * 2) + ecol * 2, *(uint32_t*)&p23);
            }
            NAMED_BAR(1 + rgrp, 64);
#pragma unroll
            for (int kk2 = 0; kk2 < 4; kk2++) {
                int ka = kk2 * 16;
                uint32_t a0[4], a1[4];
                ldsm_x4(a0, sb + SM_E + (mbase + (lane & 15)) * (ES * 2)
                                + (ka + ((lane >> 4) << 3)) * 2);
                ldsm_x4(a1, sb + SM_E + (mbase + 16 + (lane & 15)) * (ES * 2)
                                + (ka + ((lane >> 4) << 3)) * 2);
                int jrow = hf * 64 + ka + (lane & 7) + (lane & 8);
#pragma unroll
                for (int t2 = 0; t2 < 8; t2++) {
                    uint32_t b[4];
                    int cc = chalf * 128 + t2 * 16 + ((lane & 16) >> 1);
                    ldsm_x4_t(b, sQj + jrow * (QS * 2) + cc * 2);
                    mma_bf16(&d2[(2 * t2) * 4],          a0, b[0], b[1]);
                    mma_bf16(&d2[(2 * t2 + 1) * 4],      a0, b[2], b[3]);
                    mma_bf16(&d2[(16 + 2 * t2) * 4],     a1, b[0], b[1]);
                    mma_bf16(&d2[(16 + 2 * t2 + 1) * 4], a1, b[2], b[3]);
                }
            }
            NAMED_BAR(1 + rgrp, 64);
        }
    }

    // ---- writeout: D2 partials in bf16 -------------------------------------
    {
        size_t rb0 = (size_t)split * NPAD + i0 + mbase + (lane >> 2);
#pragma unroll
        for (int mt = 0; mt < 2; mt++) {
            size_t rbase = rb0 + mt * 16;
#pragma unroll
            for (int nn = 0; nn < 16; nn++) {
                int col = chalf * 128 + nn * 8 + ((lane & 3) << 1);
                int idx = (mt * 16 + nn) * 4;
                __nv_bfloat162 p0 = __floats2bfloat162_rn(d2[idx], d2[idx + 1]);
                __nv_bfloat162 p1 = __floats2bfloat162_rn(d2[idx + 2], d2[idx + 3]);
                *(uint32_t*)&g_part[rbase * C2 + col]       = *(uint32_t*)&p0;
                *(uint32_t*)&g_part[(rbase + 8) * C2 + col] = *(uint32_t*)&p1;
            }
        }
    }
#pragma unroll
    for (int q = 0; q < 4; q++) {
        den[q] += __shfl_xor_sync(0xffffffffu, den[q], 1);
        den[q] += __shfl_xor_sync(0xffffffffu, den[q], 2);
    }
    if ((lane & 3) == 0) {
        float* db = (float*)(smem + SM_DENB) + chalf * IBLK;
#pragma unroll
        for (int mt = 0; mt < 2; mt++) {
            db[mbase + mt * 16 + (lane >> 2)]     = den[mt * 2 + 0];
            db[mbase + mt * 16 + 8 + (lane >> 2)] = den[mt * 2 + 1];
        }
    }
    __syncthreads();
    if (tid < IBLK) {
        const float* db = (const float*)(smem + SM_DENB);
        g_denp[split * NPAD + i0 + tid] = db[tid] + db[IBLK + tid];
    }
}

__global__ void k_invden() {
    int i = blockIdx.x * blockDim.x + threadIdx.x;
    if (i < N_ITEMS) {
        float s = (float)NPAD;
#pragma unroll
        for (int sp = 0; sp < RJS; sp++) s += g_denp[sp * NPAD + i];
        g_invden[i] = 1.f / s;
    }
}

// CAT[i] = [emb_item[i] | region[i]],  region = (colsum + sum_splits D2) / den
__global__ void k_cat(const float* __restrict__ emb_item) {
    int gid = blockIdx.x * blockDim.x + threadIdx.x;
    if (gid < N_ITEMS * D3) {
        int i = gid / D3, d = gid % D3;
        float v;
        if (d < DD) {
            v = emb_item[(size_t)i * DD + d];
        } else {
            int c = d - DD;
            float s = g_colsum[c];
#pragma unroll
            for (int sp = 0; sp < RJS; sp++)
                s += __bfloat162float(g_part[((size_t)sp * NPAD + i) * C2 + c]);
            v = s * g_invden[i];
        }
        g_cat[gid] = v;
        g_catb[gid] = __float2bfloat16(v);
    }
}

// ---- shared GEMM tile body (device function) -------------------------------
__device__ __forceinline__ void gemm_pass(const __nv_bfloat16* __restrict__ A,
                                          const __nv_bfloat16* __restrict__ B,
                                          float s[8][4],
                                          __nv_bfloat16 (*As)[72],
                                          __nv_bfloat16 (*Bs)[72],
                                          uint32_t sa, uint32_t sbb,
                                          int bm, int bn, int M,
                                          int tid, int warp, int lane,
                                          int mrow, int nc) {
    for (int kt = 0; kt < D3; kt += 64) {
        __syncthreads();
#pragma unroll
        for (int it = 0; it < 2; it++) {
            int idx = it * 256 + tid;
            int row = idx >> 3, c8 = (idx & 7) * 8;
            int gm = bm + row;
            uint4 v = make_uint4(0u, 0u, 0u, 0u);
            if (gm < M) v = *(const uint4*)(A + (size_t)gm * D3 + kt + c8);
            *(uint4*)(&As[row][c8]) = v;
        }
#pragma unroll
        for (int it = 0; it < 4; it++) {
            int idx = it * 256 + tid;
            int row = idx >> 3, c8 = (idx & 7) * 8;
            uint4 v = *(const uint4*)(B + (size_t)(bn + row) * D3 + kt + c8);
            *(uint4*)(&Bs[row][c8]) = v;
        }
        __syncthreads();
#pragma unroll
        for (int kk = 0; kk < 4; kk++) {
            uint32_t a[4];
            ldsm_x4(a, sa + ((mrow + (lane & 15)) * 72 + kk * 16 + ((lane >> 4) << 3)) * 2);
#pragma unroll
            for (int t = 0; t < 4; t++) {
                uint32_t b[4];
                int nrow = nc + t * 16 + (lane & 7) + ((lane & 16) >> 1);
                int bc = kk * 16 + (lane & 8);
                ldsm_x4(b, sbb + (nrow * 72 + bc) * 2);
                mma_bf16(s[2 * t],     a, b[0], b[1]);
                mma_bf16(s[2 * t + 1], a, b[2], b[3]);
            }
        }
    }
}

// ---- bf16 tensor-core GEMM: C[M,384] = A[M,384] @ B[384,384]^T (+ bias) ----
__global__ __launch_bounds__(256) void k_gemm_bf(const __nv_bfloat16* __restrict__ A,
                                                 const __nv_bfloat16* __restrict__ B,
                                                 const float* __restrict__ bias,
                                                 float* __restrict__ C,
                                                 __nv_bfloat16* __restrict__ Cb,
                                                 int M) {
    __shared__ __nv_bfloat16 As[64][72];
    __shared__ __nv_bfloat16 Bs[128][72];
    int tid = threadIdx.x;
    int warp = tid >> 5, lane = tid & 31;
    int bm = blockIdx.x * 64, bn = blockIdx.y * 128;
    const int mrow = (warp >> 1) * 16, nc = (warp & 1) * 64;
    uint32_t sa = smem_to_u32(As), sbb = smem_to_u32(Bs);
    float s[8][4];
#pragma unroll
    for (int t = 0; t < 8; t++)
#pragma unroll
        for (int k = 0; k < 4; k++) s[t][k] = 0.f;

    gemm_pass(A, B, s, As, Bs, sa, sbb, bm, bn, M, tid, warp, lane, mrow, nc);

    int gm0 = bm + mrow + (lane >> 2);
#pragma unroll
    for (int t = 0; t < 8; t++) {
        int col = bn + nc + t * 8 + ((lane & 3) << 1);
        float b0 = bias ? bias[col] : 0.f;
        float b1 = bias ? bias[col + 1] : 0.f;
        float v00 = s[t][0] + b0, v01 = s[t][1] + b1;
        float v10 = s[t][2] + b0, v11 = s[t][3] + b1;
        if (gm0 < M) {
            if (C) *(float2*)&C[(size_t)gm0 * D3 + col] = make_float2(v00, v01);
            if (Cb) {
                __nv_bfloat162 p = __floats2bfloat162_rn(v00, v01);
                *(uint32_t*)&Cb[(size_t)gm0 * D3 + col] = *(uint32_t*)&p;
            }
        }
        if (gm0 + 8 < M) {
            if (C) *(float2*)&C[(size_t)(gm0 + 8) * D3 + col] = make_float2(v10, v11);
            if (Cb) {
                __nv_bfloat162 p = __floats2bfloat162_rn(v10, v11);
                *(uint32_t*)&Cb[(size_t)(gm0 + 8) * D3 + col] = *(uint32_t*)&p;
            }
        }
    }
}

// ---- merged tgt GEMMs: z=0 -> qp (1 pass + bias); z=1 -> uv (split-bf16 x3)
__global__ __launch_bounds__(256) void k_gemm_tgt(const __nv_bfloat16* __restrict__ Ah,
                                                  const __nv_bfloat16* __restrict__ Al,
                                                  const __nv_bfloat16* __restrict__ Wq,
                                                  const float* __restrict__ bq,
                                                  float* __restrict__ Cqp,
                                                  const __nv_bfloat16* __restrict__ Bh,
                                                  const __nv_bfloat16* __restrict__ Bl,
                                                  float* __restrict__ Cuv, int M) {
    __shared__ __nv_bfloat16 As[64][72];
    __shared__ __nv_bfloat16 Bs[128][72];
    int tid = threadIdx.x;
    int warp = tid >> 5, lane = tid & 31;
    int bm = blockIdx.x * 64, bn = blockIdx.y * 128;
    const int mrow = (warp >> 1) * 16, nc = (warp & 1) * 64;
    uint32_t sa = smem_to_u32(As), sbb = smem_to_u32(Bs);
    float s[8][4];
#pragma unroll
    for (int t = 0; t < 8; t++)
#pragma unroll
        for (int k = 0; k < 4; k++) s[t][k] = 0.f;

    int gm0 = bm + mrow + (lane >> 2);
    if (blockIdx.z == 0) {
        gemm_pass(Ah, Wq, s, As, Bs, sa, sbb, bm, bn, M, tid, warp, lane, mrow, nc);
#pragma unroll
        for (int t = 0; t < 8; t++) {
            int col = bn + nc + t * 8 + ((lane & 3) << 1);
            float b0 = bq[col], b1 = bq[col + 1];
            if (gm0 < M)
                *(float2*)&Cqp[(size_t)gm0 * D3 + col] =
                    make_float2(s[t][0] + b0, s[t][1] + b1);
            if (gm0 + 8 < M)
                *(float2*)&Cqp[(size_t)(gm0 + 8) * D3 + col] =
                    make_float2(s[t][2] + b0, s[t][3] + b1);
        }
    } else {
        gemm_pass(Ah, Bh, s, As, Bs, sa, sbb, bm, bn, M, tid, warp, lane, mrow, nc);
        gemm_pass(Al, Bh, s, As, Bs, sa, sbb, bm, bn, M, tid, warp, lane, mrow, nc);
        gemm_pass(Ah, Bl, s, As, Bs, sa, sbb, bm, bn, M, tid, warp, lane, mrow, nc);
#pragma unroll
        for (int t = 0; t < 8; t++) {
            int col = bn + nc + t * 8 + ((lane & 3) << 1);
            if (gm0 < M)
                *(float2*)&Cuv[(size_t)gm0 * D3 + col] = make_float2(s[t][0], s[t][1]);
            if (gm0 + 8 < M)
                *(float2*)&Cuv[(size_t)(gm0 + 8) * D3 + col] = make_float2(s[t][2], s[t][3]);
        }
    }
}

__global__ void k_tgt(const int* __restrict__ item_i, const int* __restrict__ item_j) {
    int gid = blockIdx.x * blockDim.x + threadIdx.x;
    if (gid < 2 * NBATCH * D3) {
        int row = gid / D3, d = gid % D3;
        int idx = (row < NBATCH) ? item_i[row] : item_j[row - NBATCH];
        float v = g_cat[(size_t)idx * D3 + d];
        g_tgt[gid] = v;
        __nv_bfloat16 hi = __float2bfloat16(v);
        g_tgtb[gid] = hi;
        g_tgtl[gid] = __float2bfloat16(v - __bfloat162float(hi));
    }
}

// per-batch final: shared-row gathers (1 load, 2 FMAs), d-range split across groups
__global__ __launch_bounds__(256) void k_final(const int* __restrict__ user,
                                               const int* __restrict__ item_i,
                                               const float* __restrict__ bv,
                                               float* __restrict__ out) {
    __shared__ int   us[HIST];
    __shared__ float qb[2][D3], ub[2][D3];
    __shared__ float sp_s[2][2][HIST];
    __shared__ float sp_a[2][2][HIST];
    __shared__ float ev[2][HIST], evt[2][HIST];
    __shared__ float bvp[2][8];
    __shared__ float bvd[2];
    int b = blockIdx.x, t = threadIdx.x;
    int lane = t & 31, warp = t >> 5;
    if (t < HIST) us[t] = user[b * HIST + t];
    for (int i = t; i < D3; i += 256) {
        qb[0][i] = g_qp[(size_t)b * D3 + i];
        qb[1][i] = g_qp[(size_t)(NBATCH + b) * D3 + i];
        ub[0][i] = g_uv[(size_t)b * D3 + i];
        ub[1][i] = g_uv[(size_t)(NBATCH + b) * D3 + i];
    }
    {
        float pp = 0.f, pn = 0.f;
        for (int d = t; d < D3; d += 256) {
            float bb = bv[d];
            pp = fmaf(bb, g_tgt[(size_t)b * D3 + d], pp);
            pn = fmaf(bb, g_tgt[(size_t)(NBATCH + b) * D3 + d], pn);
        }
#pragma unroll
        for (int o = 16; o; o >>= 1) {
            pp += __shfl_xor_sync(0xffffffffu, pp, o);
            pn += __shfl_xor_sync(0xffffffffu, pn, o);
        }
        if (lane == 0) { bvp[0][warp] = pp; bvp[1][warp] = pn; }
    }
    __syncthreads();
    if (t < 2) {
        float s = 0.f;
#pragma unroll
        for (int w = 0; w < 8; w++) s += bvp[t][w];
        bvd[t] = s;
    }
    int h = -1, l = 0;
    if (t < HIST) { h = 0; l = t; }
    else if (t >= 128 && t < 128 + HIST) { h = 1; l = t - 128; }
    if (h >= 0) {
        float sp = 0.f, sn = 0.f;
        int r = h ? 50 : 0, cc = l;
        int d = h * 192;
#pragma unroll 4
        for (int i = 0; i < 192; i++) {
            float kev = __bfloat162float(g_keb[(size_t)us[r] * D3 + cc]);
            sp = fmaf(qb[0][d], kev, sp);
            sn = fmaf(qb[1][d], kev, sn);
            d++;
            cc += 100;
            if (cc >= D3) { cc -= D3; r++; }
        }
        sp_s[h][0][l] = sp;
        sp_s[h][1][l] = sn;
        const float* crow = &g_cat[(size_t)us[l] * D3];
        float ap = 0.f, an = 0.f;
        int d0 = h * 192;
#pragma unroll 4
        for (int i = 0; i < 192; i++) {
            float cv = crow[d0 + i];
            ap = fmaf(cv, ub[0][d0 + i], ap);
            an = fmaf(cv, ub[1][d0 + i], an);
        }
        sp_a[h][0][l] = ap;
        sp_a[h][1][l] = an;
    }
    __syncthreads();
    if (t < 2 * HIST) {
        int l2 = t % HIST, br = t / HIST;
        float s = (sp_s[0][br][l2] + sp_s[1][br][l2]) * 0.0510310363f;
        float tv = sp_a[0][br][l2] + sp_a[1][br][l2] + bvd[br];
        float e = expf(s);
        if (br == 0 && us[l2] == item_i[b]) e = 0.f;
        ev[br][l2]  = e;
        evt[br][l2] = e * tv;
    }
    __syncthreads();
    if (t < 2) {
        float se = 0.f, st = 0.f;
        for (int l2 = 0; l2 < HIST; l2++) { se += ev[t][l2]; st += evt[t][l2]; }
        out[(size_t)t * NBATCH + b] = st / sqrtf(se);
    }
}

// ------------- eager preload: module, kernels, local-mem pools --------------
static float* p_cat = nullptr;
static __nv_bfloat16* p_catb = nullptr;
static __nv_bfloat16* p_keb = nullptr;
static float* p_tgt = nullptr;
static __nv_bfloat16* p_tgtb = nullptr;
static __nv_bfloat16* p_tgtl = nullptr;
static float* p_qp  = nullptr;
static float* p_uv  = nullptr;
static __nv_bfloat16* p_wkb = nullptr;
static __nv_bfloat16* p_wqb = nullptr;
static __nv_bfloat16* p_wvh = nullptr;
static __nv_bfloat16* p_wvl = nullptr;
static __nv_bfloat16* p_part = nullptr;
static cudaStream_t s2;
static cudaEvent_t ev1, ev2, ev3, ev4;

namespace {
struct Preload {
    Preload() {
        cudaFree(0);
        cudaStreamCreateWithFlags(&s2, cudaStreamNonBlocking);
        cudaEventCreateWithFlags(&ev1, cudaEventDisableTiming);
        cudaEventCreateWithFlags(&ev2, cudaEventDisableTiming);
        cudaEventCreateWithFlags(&ev3, cudaEventDisableTiming);
        cudaEventCreateWithFlags(&ev4, cudaEventDisableTiming);
        cudaGetSymbolAddress((void**)&p_part, g_part);
        cudaGetSymbolAddress((void**)&p_cat, g_cat);
        cudaGetSymbolAddress((void**)&p_catb, g_catb);
        cudaGetSymbolAddress((void**)&p_keb, g_keb);
        cudaGetSymbolAddress((void**)&p_tgt, g_tgt);
        cudaGetSymbolAddress((void**)&p_tgtb, g_tgtb);
        cudaGetSymbolAddress((void**)&p_tgtl, g_tgtl);
        cudaGetSymbolAddress((void**)&p_qp,  g_qp);
        cudaGetSymbolAddress((void**)&p_uv,  g_uv);
        cudaGetSymbolAddress((void**)&p_wkb, g_wkb);
        cudaGetSymbolAddress((void**)&p_wqb, g_wqb);
        cudaGetSymbolAddress((void**)&p_wvh, g_wvh);
        cudaGetSymbolAddress((void**)&p_wvl, g_wvl);
        cudaFuncAttributes fa;
        cudaFuncGetAttributes(&fa, k_prep);
        cudaFuncGetAttributes(&fa, k_colsum);
        cudaFuncGetAttributes(&fa, k_colred);
        cudaFuncGetAttributes(&fa, k_wprep);
        cudaFuncGetAttributes(&fa, k_flash);
        cudaFuncGetAttributes(&fa, k_invden);
        cudaFuncGetAttributes(&fa, k_cat);
        cudaFuncGetAttributes(&fa, k_gemm_bf);
        cudaFuncGetAttributes(&fa, k_gemm_tgt);
        cudaFuncGetAttributes(&fa, k_tgt);
        cudaFuncGetAttributes(&fa, k_final);
        cudaFuncSetAttribute(k_flash, cudaFuncAttributeMaxDynamicSharedMemorySize, SM_TOT);
        cudaMemset(p_part, 0, 8u << 20);
        int*   zints = (int*)p_part;
        float* zf    = (float*)p_part;
        float* fout  = (float*)p_part + (1u << 20);
        k_prep<<<1, 256>>>(zf, zf);
        k_colsum<<<1, 256>>>();
        k_colred<<<1, 256>>>();
        k_wprep<<<1, 256>>>(zf, zf, zf);
        k_flash<<<dim3(1, 1), 256, SM_TOT>>>();
        k_invden<<<1, 256>>>();
        k_cat<<<1, 256>>>(zf);
        k_gemm_bf<<<dim3(1, 1), 256>>>(p_catb, p_wkb, (const float*)nullptr,
                                       (float*)nullptr, p_keb, 64);
        k_gemm_tgt<<<dim3(1, 1, 2), 256>>>(p_tgtb, p_tgtl, p_wqb, zf, p_qp,
                                           p_wvh, p_wvl, p_uv, 64);
        k_tgt<<<1, 256>>>(zints, zints);
        k_final<<<1, 256>>>(zints, zints, zf, fout);
        // also warm the kernels on s2 (local-mem pools are per-device; harmless)
        k_colsum<<<1, 256, 0, s2>>>();
        cudaDeviceSynchronize();
    }
};
Preload preload_instance_;
}  // namespace

// ---------------------------------------------------------------------------
extern "C" void kernel_launch(void* const* d_in, const int* in_sizes, int n_in,
                              void* d_out, int out_size) {
    const int*   user      = (const int*)d_in[0];
    const int*   item_i    = (const int*)d_in[1];
    const int*   item_j    = (const int*)d_in[2];
    const float* emb_item  = (const float*)d_in[3];
    const float* emb_in    = (const float*)d_in[4];
    const float* emb_out   = (const float*)d_in[5];
    const float* Wq        = (const float*)d_in[6];
    const float* bq        = (const float*)d_in[7];
    const float* Wk        = (const float*)d_in[8];
    const float* bk        = (const float*)d_in[9];
    const float* Wv        = (const float*)d_in[10];
    const float* bv        = (const float*)d_in[11];
    float* out = (float*)d_out;

    k_prep<<<(NPAD * C2 + 255) / 256, 256>>>(emb_in, emb_out);
    cudaEventRecord(ev1, 0);

    // side stream: colsum/colred (need g_qbf) + wprep, concurrent with k_flash
    cudaStreamWaitEvent(s2, ev1, 0);
    k_colsum<<<NCHUNK, 256, 0, s2>>>();
    k_colred<<<1, 256, 0, s2>>>();
    k_wprep<<<(D3 * D3 + 255) / 256, 256, 0, s2>>>(Wk, Wq, Wv);
    cudaEventRecord(ev2, s2);

    k_flash<<<dim3(NIB, RJS), 256, SM_TOT>>>();

    k_invden<<<(N_ITEMS + 255) / 256, 256>>>();
    cudaStreamWaitEvent(0, ev2, 0);   // k_cat needs colsum; KE needs wkb
    k_cat<<<(N_ITEMS * D3 + 255) / 256, 256>>>(emb_item);
    cudaEventRecord(ev3, 0);

    // legacy: KE GEMM; s2: tgt gather + merged tgt GEMMs (independent of KE)
    k_gemm_bf<<<dim3(157, 3), 256>>>(p_catb, p_wkb, bk, (float*)nullptr, p_keb, N_ITEMS);

    cudaStreamWaitEvent(s2, ev3, 0);
    k_tgt<<<(2 * NBATCH * D3 + 255) / 256, 256, 0, s2>>>(item_i, item_j);
    k_gemm_tgt<<<dim3(32, 3, 2), 256, 0, s2>>>(p_tgtb, p_tgtl, p_wqb, bq, p_qp,
                                               p_wvh, p_wvl, p_uv, 2 * NBATCH);
    cudaEventRecord(ev4, s2);

    cudaStreamWaitEvent(0, ev4, 0);
    k_final<<<NBATCH, 256>>>(user, item_i, bv, out);
}